// round 11
// baseline (speedup 1.0000x reference)
#include <cuda_runtime.h>
#include <cuda_bf16.h>
#include <cstdint>

#define BB 4
#define CN 256
#define NN 4096
#define OTOT 320
#define BN_TOT 16384.0f
#define KTOT 16384

// ---------------- device scratch ----------------
__device__ float g_mx[CN];                            // raw channel sums
__device__ float g_G[CN * CN];
__device__ float g_Bf[OTOT];
__device__ __nv_bfloat16 g_Wh[OTOT * CN];             // folded W hi, [o][c]
__device__ __nv_bfloat16 g_Wl[OTOT * CN];             // folded W lo, [o][c]
__device__ __nv_bfloat16 g_xh[(size_t)CN * KTOT];     // x hi, [c][b*n]
__device__ __nv_bfloat16 g_xl[(size_t)CN * KTOT];     // x lo, [c][b*n]
__device__ __nv_bfloat16 g_xTh[(size_t)KTOT * CN];    // x hi, [b*n][c]
__device__ __nv_bfloat16 g_xTl[(size_t)KTOT * CN];    // x lo, [b*n][c]
__device__ __nv_bfloat16 g_Qb[(size_t)BB * NN * 128]; // [b][n][qhi32|qlo32|qhi32|0]
__device__ __nv_bfloat16 g_Kb[(size_t)BB * NN * 128]; // [b][n][khi32|khi32|klo32|0]
__device__ __nv_bfloat16 g_Vb[(size_t)BB * CN * NN];  // bf16, [b][c][n]

// ---------------- mma.sync / async helpers ----------------
__device__ __forceinline__ void mma_bf16_16816(float* c, uint32_t a0, uint32_t a1,
                                               uint32_t a2, uint32_t a3,
                                               uint32_t b0, uint32_t b1) {
    asm volatile("mma.sync.aligned.m16n8k16.row.col.f32.bf16.bf16.f32 "
        "{%0,%1,%2,%3}, {%4,%5,%6,%7}, {%8,%9}, {%0,%1,%2,%3};"
        : "+f"(c[0]), "+f"(c[1]), "+f"(c[2]), "+f"(c[3])
        : "r"(a0), "r"(a1), "r"(a2), "r"(a3), "r"(b0), "r"(b1));
}
__device__ __forceinline__ void cp16(uint32_t dst, const void* src) {
    asm volatile("cp.async.cg.shared.global [%0], [%1], 16;" :: "r"(dst), "l"(src));
}
#define CP_COMMIT() asm volatile("cp.async.commit_group;" ::: "memory")
#define CP_WAIT0()  asm volatile("cp.async.wait_group 0;" ::: "memory")
__device__ __forceinline__ uint32_t smem_u32(const void* p) {
    uint32_t a;
    asm("{ .reg .u64 t; cvta.to.shared.u64 t, %1; cvt.u32.u64 %0, t; }" : "=r"(a) : "l"(p));
    return a;
}
__device__ __forceinline__ uint32_t pack_bf2(float a, float b) {
    __nv_bfloat162 h = __floats2bfloat162_rn(a, b);
    return *(uint32_t*)&h;
}

// ---------------- prologue ----------------
__global__ void zero_kernel() {
    int i = blockIdx.x * blockDim.x + threadIdx.x;
    g_G[i] = 0.0f;
    if (i < CN) g_mx[i] = 0.0f;
}

// tiled transpose/convert: x -> bf16 hi/lo in [c][bn] AND [bn][c]; fused channel sums
__global__ void convx_kernel(const float* __restrict__ x) {
    __shared__ float tile[64][65];
    int n0 = blockIdx.x * 64, c0 = blockIdx.y * 64, b = blockIdx.z;
    int tid = threadIdx.x;
    int rr = tid >> 6, jj = tid & 63;
    const float* xb = x + ((size_t)b * CN + c0) * NN + n0;
    #pragma unroll
    for (int r = 0; r < 16; ++r) {
        int i = r * 4 + rr;
        tile[i][jj] = xb[(size_t)i * NN + jj];
    }
    __syncthreads();
    if (tid < 64) {
        float s = 0.0f;
        #pragma unroll
        for (int j = 0; j < 64; ++j) s += tile[tid][j];
        atomicAdd(&g_mx[c0 + tid], s);
    }
    size_t bn0 = (size_t)b * NN + n0;
    #pragma unroll
    for (int r = 0; r < 16; ++r) {
        int i = r * 4 + rr;
        float v = tile[i][jj];
        __nv_bfloat16 hi = __float2bfloat16(v);
        __nv_bfloat16 lo = __float2bfloat16(v - __bfloat162float(hi));
        size_t off = (size_t)(c0 + i) * KTOT + bn0 + jj;
        g_xh[off] = hi; g_xl[off] = lo;
    }
    #pragma unroll
    for (int r = 0; r < 16; ++r) {
        int i = r * 4 + rr;           // n index
        float v = tile[jj][i];        // [c=jj][n=i]
        __nv_bfloat16 hi = __float2bfloat16(v);
        __nv_bfloat16 lo = __float2bfloat16(v - __bfloat162float(hi));
        size_t off = (bn0 + i) * CN + c0 + jj;
        g_xTh[off] = hi; g_xTl[off] = lo;
    }
}

// ---------------- Gram via mma.sync (hi/lo, symmetric: upper-triangle tiles only) ----------------
#define GR_STRIDE 144
#define GR_MAT (64 * GR_STRIDE)
__global__ void __launch_bounds__(256, 2)
gram_mma(int dummy) {
    __shared__ __align__(16) char smem[4 * GR_MAT];
    uint32_t sb = smem_u32(smem);
    int tid = threadIdx.x;
    int lane = tid & 31, wid = tid >> 5;
    int g = lane >> 2, t = lane & 3;
    int wm = wid >> 2, wn = wid & 3;
    // map blockIdx.x (0..9) -> upper-triangle pair (r, c), r <= c
    int r4 = 0, rem = blockIdx.x;
    while (rem >= 4 - r4) { rem -= 4 - r4; ++r4; }
    int c4 = r4 + rem;
    int c0 = r4 * 64, c1 = c4 * 64;
    int kseg = blockIdx.z * 1024;

    float C[2][2][4] = {};

    for (int ch = 0; ch < 16; ++ch) {
        int k0 = kseg + ch * 64;
        __syncthreads();
        #pragma unroll
        for (int i = tid; i < 512; i += 256) {
            int row = i >> 3, col = i & 7;
            cp16(sb + 0 * GR_MAT + row * GR_STRIDE + col * 16,
                 g_xh + (size_t)(c0 + row) * KTOT + k0 + col * 8);
            cp16(sb + 1 * GR_MAT + row * GR_STRIDE + col * 16,
                 g_xl + (size_t)(c0 + row) * KTOT + k0 + col * 8);
            cp16(sb + 2 * GR_MAT + row * GR_STRIDE + col * 16,
                 g_xh + (size_t)(c1 + row) * KTOT + k0 + col * 8);
            cp16(sb + 3 * GR_MAT + row * GR_STRIDE + col * 16,
                 g_xl + (size_t)(c1 + row) * KTOT + k0 + col * 8);
        }
        CP_COMMIT();
        CP_WAIT0();
        __syncthreads();
        const char* Ah = smem;
        const char* Al = smem + GR_MAT;
        const char* Bh = smem + 2 * GR_MAT;
        const char* Bl = smem + 3 * GR_MAT;
        #pragma unroll
        for (int ks = 0; ks < 4; ++ks) {
            int koff = ks * 32 + t * 4;
            uint32_t ah[2][4], al[2][4];
            #pragma unroll
            for (int fm = 0; fm < 2; ++fm) {
                int r = wm * 32 + fm * 16 + g;
                ah[fm][0] = *(const uint32_t*)(Ah + r * GR_STRIDE + koff);
                ah[fm][1] = *(const uint32_t*)(Ah + (r + 8) * GR_STRIDE + koff);
                ah[fm][2] = *(const uint32_t*)(Ah + r * GR_STRIDE + koff + 16);
                ah[fm][3] = *(const uint32_t*)(Ah + (r + 8) * GR_STRIDE + koff + 16);
                al[fm][0] = *(const uint32_t*)(Al + r * GR_STRIDE + koff);
                al[fm][1] = *(const uint32_t*)(Al + (r + 8) * GR_STRIDE + koff);
                al[fm][2] = *(const uint32_t*)(Al + r * GR_STRIDE + koff + 16);
                al[fm][3] = *(const uint32_t*)(Al + (r + 8) * GR_STRIDE + koff + 16);
            }
            #pragma unroll
            for (int fn = 0; fn < 2; ++fn) {
                int r = wn * 16 + fn * 8 + g;
                uint32_t bh0 = *(const uint32_t*)(Bh + r * GR_STRIDE + koff);
                uint32_t bh1 = *(const uint32_t*)(Bh + r * GR_STRIDE + koff + 16);
                uint32_t bl0 = *(const uint32_t*)(Bl + r * GR_STRIDE + koff);
                uint32_t bl1 = *(const uint32_t*)(Bl + r * GR_STRIDE + koff + 16);
                #pragma unroll
                for (int fm = 0; fm < 2; ++fm) {
                    mma_bf16_16816(C[fm][fn], ah[fm][0], ah[fm][1], ah[fm][2], ah[fm][3], bh0, bh1);
                    mma_bf16_16816(C[fm][fn], ah[fm][0], ah[fm][1], ah[fm][2], ah[fm][3], bl0, bl1);
                    mma_bf16_16816(C[fm][fn], al[fm][0], al[fm][1], al[fm][2], al[fm][3], bh0, bh1);
                }
            }
        }
    }
    int mirror = (c0 != c1);
    #pragma unroll
    for (int fm = 0; fm < 2; ++fm) {
        #pragma unroll
        for (int fn = 0; fn < 2; ++fn) {
            int r0 = c0 + wm * 32 + fm * 16 + g;
            int cc = c1 + wn * 16 + fn * 8 + 2 * t;
            atomicAdd(&g_G[r0 * CN + cc],           C[fm][fn][0]);
            atomicAdd(&g_G[r0 * CN + cc + 1],       C[fm][fn][1]);
            atomicAdd(&g_G[(r0 + 8) * CN + cc],     C[fm][fn][2]);
            atomicAdd(&g_G[(r0 + 8) * CN + cc + 1], C[fm][fn][3]);
            if (mirror) {
                atomicAdd(&g_G[cc * CN + r0],           C[fm][fn][0]);
                atomicAdd(&g_G[(cc + 1) * CN + r0],     C[fm][fn][1]);
                atomicAdd(&g_G[cc * CN + r0 + 8],       C[fm][fn][2]);
                atomicAdd(&g_G[(cc + 1) * CN + r0 + 8], C[fm][fn][3]);
            }
        }
    }
}

// ---------------- fold BN: 8 outputs per block, G tiled through smem ----------------
__global__ void __launch_bounds__(256, 2)
fold_kernel(const float* __restrict__ w1, const float* __restrict__ w2,
            const float* __restrict__ w3,
            const float* __restrict__ g1, const float* __restrict__ b1,
            const float* __restrict__ g2, const float* __restrict__ b2,
            const float* __restrict__ g3, const float* __restrict__ b3) {
    int o0 = blockIdx.x * 8;
    int tid = threadIdx.x;
    int lane = tid & 31, wid = tid >> 5;
    __shared__ float ws[8][256];
    __shared__ float Gt[32][257];
    __shared__ float sE[8][264];
    __shared__ float sM[8][264];
    __shared__ float scs[8];
    __shared__ float ggs[8], bbs[8];

    #pragma unroll
    for (int oo = 0; oo < 8; ++oo) {
        int o = o0 + oo;
        const float* w;
        if (o < 32)      w = w1 + o * CN;
        else if (o < 64) w = w2 + (o - 32) * CN;
        else             w = w3 + (o - 64) * CN;
        ws[oo][tid] = w[tid];
    }
    if (tid < 8) {
        int o = o0 + tid;
        if (o < 32)      { ggs[tid] = g1[o];      bbs[tid] = b1[o]; }
        else if (o < 64) { ggs[tid] = g2[o - 32]; bbs[tid] = b2[o - 32]; }
        else             { ggs[tid] = g3[o - 64]; bbs[tid] = b3[o - 64]; }
    }
    __syncthreads();

    float acc[8] = {};
    for (int tile = 0; tile < 8; ++tile) {
        #pragma unroll
        for (int r = tid >> 5; r < 32; r += 8) {
            // warp wid loads rows r = wid, wid+8, ... cols lane*8..+8
            #pragma unroll
            for (int jj = 0; jj < 8; ++jj)
                Gt[r][lane * 8 + jj] = g_G[(tile * 32 + r) * CN + lane * 8 + jj];
        }
        __syncthreads();
        #pragma unroll 8
        for (int r = 0; r < 32; ++r) {
            float gv = Gt[r][tid];
            int c = tile * 32 + r;
            #pragma unroll
            for (int oo = 0; oo < 8; ++oo) acc[oo] += gv * ws[oo][c];
        }
        __syncthreads();
    }
    #pragma unroll
    for (int oo = 0; oo < 8; ++oo) {
        sE[oo][tid] = acc[oo] * ws[oo][tid];
        sM[oo][tid] = ws[oo][tid] * g_mx[tid] * (1.0f / BN_TOT);
    }
    __syncthreads();
    if (wid < 8) {
        float e = 0.0f, m = 0.0f;
        #pragma unroll
        for (int j = lane; j < 256; j += 32) { e += sE[wid][j]; m += sM[wid][j]; }
        #pragma unroll
        for (int st = 16; st > 0; st >>= 1) {
            e += __shfl_xor_sync(0xffffffffu, e, st);
            m += __shfl_xor_sync(0xffffffffu, m, st);
        }
        if (lane == 0) {
            float E = e * (1.0f / BN_TOT);
            float rs = rsqrtf(E - m * m + 1e-5f);
            float sc = ggs[wid] * rs;
            scs[wid] = sc;
            g_Bf[o0 + wid] = bbs[wid] - sc * m;
        }
    }
    __syncthreads();
    #pragma unroll
    for (int oo = 0; oo < 8; ++oo) {
        float wf = scs[oo] * ws[oo][tid];
        __nv_bfloat16 hi = __float2bfloat16(wf);
        __nv_bfloat16 lo = __float2bfloat16(wf - __bfloat162float(hi));
        g_Wh[(o0 + oo) * CN + tid] = hi;
        g_Wl[(o0 + oo) * CN + tid] = lo;
    }
}

// ---------------- qkd via mma.sync: Z[o][bn] = relu(W x + b) -> Qb/Kb/Vb ----------------
#define QK_SM 92160
__global__ void __launch_bounds__(256, 2)
qkd_mma(int dummy) {
    extern __shared__ __align__(16) char smem[];
    uint32_t sb = smem_u32(smem);
    int tid = threadIdx.x;
    int lane = tid & 31, wid = tid >> 5;
    int g = lane >> 2, t = lane & 3;
    int wm = wid >> 2, wn = wid & 3;
    int o0 = blockIdx.x * 64;
    int bn0 = blockIdx.y * 256;

    float C[2][8][4] = {};

    for (int kc = 0; kc < 4; ++kc) {
        int k0 = kc * 64;
        __syncthreads();
        #pragma unroll
        for (int i = tid; i < 512; i += 256) {
            int row = i >> 3, col = i & 7;
            cp16(sb + row * 144 + col * 16,        g_Wh + (size_t)(o0 + row) * CN + k0 + col * 8);
            cp16(sb + 9216 + row * 144 + col * 16, g_Wl + (size_t)(o0 + row) * CN + k0 + col * 8);
        }
        #pragma unroll
        for (int i = tid; i < 2048; i += 256) {
            int row = i >> 3, col = i & 7;
            cp16(sb + 18432 + row * 144 + col * 16, g_xTh + (bn0 + row) * (size_t)CN + k0 + col * 8);
            cp16(sb + 55296 + row * 144 + col * 16, g_xTl + (bn0 + row) * (size_t)CN + k0 + col * 8);
        }
        CP_COMMIT();
        CP_WAIT0();
        __syncthreads();
        const char* Wh = smem;
        const char* Wl = smem + 9216;
        const char* Xh = smem + 18432;
        const char* Xl = smem + 55296;
        #pragma unroll
        for (int ks = 0; ks < 4; ++ks) {
            int koff = ks * 32 + t * 4;
            uint32_t ah[2][4], al[2][4];
            #pragma unroll
            for (int fm = 0; fm < 2; ++fm) {
                int r = wm * 32 + fm * 16 + g;
                ah[fm][0] = *(const uint32_t*)(Wh + r * 144 + koff);
                ah[fm][1] = *(const uint32_t*)(Wh + (r + 8) * 144 + koff);
                ah[fm][2] = *(const uint32_t*)(Wh + r * 144 + koff + 16);
                ah[fm][3] = *(const uint32_t*)(Wh + (r + 8) * 144 + koff + 16);
                al[fm][0] = *(const uint32_t*)(Wl + r * 144 + koff);
                al[fm][1] = *(const uint32_t*)(Wl + (r + 8) * 144 + koff);
                al[fm][2] = *(const uint32_t*)(Wl + r * 144 + koff + 16);
                al[fm][3] = *(const uint32_t*)(Wl + (r + 8) * 144 + koff + 16);
            }
            #pragma unroll
            for (int fn = 0; fn < 8; ++fn) {
                int r = wn * 64 + fn * 8 + g;
                uint32_t bh0 = *(const uint32_t*)(Xh + r * 144 + koff);
                uint32_t bh1 = *(const uint32_t*)(Xh + r * 144 + koff + 16);
                uint32_t bl0 = *(const uint32_t*)(Xl + r * 144 + koff);
                uint32_t bl1 = *(const uint32_t*)(Xl + r * 144 + koff + 16);
                #pragma unroll
                for (int fm = 0; fm < 2; ++fm) {
                    mma_bf16_16816(C[fm][fn], ah[fm][0], ah[fm][1], ah[fm][2], ah[fm][3], bh0, bh1);
                    mma_bf16_16816(C[fm][fn], ah[fm][0], ah[fm][1], ah[fm][2], ah[fm][3], bl0, bl1);
                    mma_bf16_16816(C[fm][fn], al[fm][0], al[fm][1], al[fm][2], al[fm][3], bh0, bh1);
                }
            }
        }
    }

    __nv_bfloat16 zero = __float2bfloat16(0.0f);
    #pragma unroll
    for (int fm = 0; fm < 2; ++fm) {
        int obase = o0 + wm * 32 + fm * 16 + g;
        float bias0 = g_Bf[obase], bias1 = g_Bf[obase + 8];
        #pragma unroll
        for (int fn = 0; fn < 8; ++fn) {
            int bncol = bn0 + wn * 64 + fn * 8 + 2 * t;
            int b = bncol >> 12, n = bncol & 4095;
            #pragma unroll
            for (int rr = 0; rr < 2; ++rr) {
                int o = obase + rr * 8;
                float v0 = fmaxf(C[fm][fn][rr * 2 + 0] + (rr ? bias1 : bias0), 0.0f);
                float v1 = fmaxf(C[fm][fn][rr * 2 + 1] + (rr ? bias1 : bias0), 0.0f);
                if (o >= 64) {
                    *(uint32_t*)(g_Vb + ((size_t)b * CN + (o - 64)) * NN + n) = pack_bf2(v0, v1);
                } else {
                    #pragma unroll
                    for (int e = 0; e < 2; ++e) {
                        float v = e ? v1 : v0;
                        __nv_bfloat16 hi = __float2bfloat16(v);
                        __nv_bfloat16 lo = __float2bfloat16(v - __bfloat162float(hi));
                        size_t base = ((size_t)b * NN + n + e) * 128;
                        if (o < 32) {
                            g_Qb[base + o] = hi; g_Qb[base + 32 + o] = lo;
                            g_Qb[base + 64 + o] = hi; g_Qb[base + 96 + o] = zero;
                        } else {
                            int oc = o - 32;
                            g_Kb[base + oc] = hi; g_Kb[base + 32 + oc] = hi;
                            g_Kb[base + 64 + oc] = lo; g_Kb[base + 96 + oc] = zero;
                        }
                    }
                }
            }
        }
    }
}

// ---------------- flash attention: channel-major PV, NT=64, 3-barrier pipeline ----------------
#define KS_OFF 0
#define KS_BUF 13312
#define VS_OFF 26624
#define VS_BUF 36864
#define PS_OFF 100352
#define STM_OFF 109568
#define STL_OFF 110080
#define STF_OFF 110592
#define FLG_OFF 110848
#define INV_OFF 110864
#define SM_TOT 111616

__global__ void __launch_bounds__(256, 2)
flash_mma(const float* __restrict__ x, float* __restrict__ out) {
    extern __shared__ __align__(16) char smem[];
    uint32_t sb = smem_u32(smem);
    int tid = threadIdx.x;
    int lane = tid & 31, wid = tid >> 5;
    int g = lane >> 2, t = lane & 3;
    int mrow = wid & 3, khalf = wid >> 2;
    int q0 = mrow * 16;
    int ch0 = wid * 32;
    int b = blockIdx.y, m0 = blockIdx.x * 64;

    float* stM = (float*)(smem + STM_OFF);
    float* stL = (float*)(smem + STL_OFF);
    float* stF = (float*)(smem + STF_OFF);
    uint32_t* flg = (uint32_t*)(smem + FLG_OFF);
    float* inv = (float*)(smem + INV_OFF);

    uint32_t qa[6][4];
    {
        const __nv_bfloat16* qr0 = g_Qb + ((size_t)b * NN + m0 + q0 + g) * 128;
        const __nv_bfloat16* qr1 = qr0 + (size_t)8 * 128;
        #pragma unroll
        for (int ks = 0; ks < 6; ++ks) {
            int e = ks * 16 + 2 * t;
            qa[ks][0] = *(const uint32_t*)(qr0 + e);
            qa[ks][1] = *(const uint32_t*)(qr1 + e);
            qa[ks][2] = *(const uint32_t*)(qr0 + e + 8);
            qa[ks][3] = *(const uint32_t*)(qr1 + e + 8);
        }
    }

    const char* kgb = (const char*)(g_Kb + ((size_t)b * NN) * 128);
    const char* vgb = (const char*)(g_Vb + (size_t)b * CN * NN);

    // prefetch chunk 0 into buf 0
    {
        #pragma unroll
        for (int i = tid; i < 768; i += 256) {
            int row = i / 12, col = i - row * 12;
            cp16(sb + KS_OFF + row * 208 + col * 16, kgb + (size_t)row * 256 + col * 16);
        }
        #pragma unroll
        for (int i = tid; i < 2048; i += 256) {
            int c = i >> 3, j = i & 7;
            cp16(sb + VS_OFF + c * 144 + j * 16, vgb + (size_t)c * (NN * 2) + j * 16);
        }
        CP_COMMIT();
    }

    float D[2][8][4];
    #pragma unroll
    for (int fm = 0; fm < 2; ++fm)
        #pragma unroll
        for (int fn = 0; fn < 8; ++fn) { D[fm][fn][0] = D[fm][fn][1] = D[fm][fn][2] = D[fm][fn][3] = 0.0f; }
    float m_run0 = -1e30f, m_run1 = -1e30f, l_run0 = 0.0f, l_run1 = 0.0f;

    for (int ch = 0; ch < 64; ++ch) {
        int buf = ch & 1;
        CP_WAIT0();        // prefetch(ch) complete (this warp's share)
        __syncthreads();   // B2: buf data visible to all; all warps done PV(ch-1)
        // prefetch ch+1 into buf^1 (safe: PV(ch-1) on that buffer finished before B2)
        if (ch + 1 < 64) {
            int n1 = (ch + 1) * 64;
            uint32_t kd = sb + KS_OFF + (buf ^ 1) * KS_BUF;
            uint32_t vd = sb + VS_OFF + (buf ^ 1) * VS_BUF;
            #pragma unroll
            for (int i = tid; i < 768; i += 256) {
                int row = i / 12, col = i - row * 12;
                cp16(kd + row * 208 + col * 16, kgb + (size_t)(n1 + row) * 256 + col * 16);
            }
            #pragma unroll
            for (int i = tid; i < 2048; i += 256) {
                int c = i >> 3, j = i & 7;
                cp16(vd + c * 144 + j * 16, vgb + (size_t)c * (NN * 2) + (size_t)n1 * 2 + j * 16);
            }
            CP_COMMIT();
        }

        // ---- score role: s[16q][32k] (keys khalf*32..+32) ----
        const char* ksm = smem + KS_OFF + buf * KS_BUF;
        float sc[4][4] = {};
        #pragma unroll
        for (int ks = 0; ks < 6; ++ks) {
            #pragma unroll
            for (int nt = 0; nt < 4; ++nt) {
                const char* kbase = ksm + (khalf * 32 + nt * 8 + g) * 208 + ks * 32 + t * 4;
                uint32_t b0 = *(const uint32_t*)(kbase);
                uint32_t b1 = *(const uint32_t*)(kbase + 16);
                mma_bf16_16816(sc[nt], qa[ks][0], qa[ks][1], qa[ks][2], qa[ks][3], b0, b1);
            }
        }
        float mp0 = fmaxf(fmaxf(sc[0][0], sc[0][1]), fmaxf(sc[1][0], sc[1][1]));
        mp0 = fmaxf(mp0, fmaxf(fmaxf(sc[2][0], sc[2][1]), fmaxf(sc[3][0], sc[3][1])));
        float mp1 = fmaxf(fmaxf(sc[0][2], sc[0][3]), fmaxf(sc[1][2], sc[1][3]));
        mp1 = fmaxf(mp1, fmaxf(fmaxf(sc[2][2], sc[2][3]), fmaxf(sc[3][2], sc[3][3])));
        mp0 = fmaxf(mp0, __shfl_xor_sync(0xffffffffu, mp0, 1));
        mp0 = fmaxf(mp0, __shfl_xor_sync(0xffffffffu, mp0, 2));
        mp1 = fmaxf(mp1, __shfl_xor_sync(0xffffffffu, mp1, 1));
        mp1 = fmaxf(mp1, __shfl_xor_sync(0xffffffffu, mp1, 2));
        if (t == 0) {
            stM[khalf * 64 + q0 + g] = mp0;
            stM[khalf * 64 + q0 + 8 + g] = mp1;
        }
        __syncthreads();   // B3: stM visible
        float mt0 = fmaxf(stM[q0 + g], stM[64 + q0 + g]);
        float mt1 = fmaxf(stM[q0 + 8 + g], stM[64 + q0 + 8 + g]);
        float mn0 = fmaxf(m_run0, mt0), mn1 = fmaxf(m_run1, mt1);
        float f0 = __expf(m_run0 - mn0), f1 = __expf(m_run1 - mn1);
        m_run0 = mn0; m_run1 = mn1;

        float ls0 = 0.0f, ls1 = 0.0f;
        #pragma unroll
        for (int nt = 0; nt < 4; ++nt) {
            float e0 = __expf(sc[nt][0] - mn0);
            float e1 = __expf(sc[nt][1] - mn0);
            float e2 = __expf(sc[nt][2] - mn1);
            float e3 = __expf(sc[nt][3] - mn1);
            ls0 += e0 + e1; ls1 += e2 + e3;
            char* pr0 = smem + PS_OFF + (q0 + g) * 144 + khalf * 64 + nt * 16 + t * 4;
            char* pr1 = smem + PS_OFF + (q0 + 8 + g) * 144 + khalf * 64 + nt * 16 + t * 4;
            *(uint32_t*)(pr0) = pack_bf2(e0, e1);
            *(uint32_t*)(pr1) = pack_bf2(e2, e3);
        }
        uint32_t nb = __ballot_sync(0xffffffffu, (f0 < 1.0f) || (f1 < 1.0f));
        if (khalf == 0 && t == 0) {
            stF[q0 + g] = f0;
            stF[q0 + 8 + g] = f1;
        }
        if (khalf == 0 && lane == 0) flg[mrow] = nb;
        ls0 += __shfl_xor_sync(0xffffffffu, ls0, 1);
        ls0 += __shfl_xor_sync(0xffffffffu, ls0, 2);
        ls1 += __shfl_xor_sync(0xffffffffu, ls1, 1);
        ls1 += __shfl_xor_sync(0xffffffffu, ls1, 2);
        if (t == 0) {
            stL[khalf * 64 + q0 + g] = ls0;
            stL[khalf * 64 + q0 + 8 + g] = ls1;
        }
        __syncthreads();   // B4: Ps both halves + stL + stF + flags visible
        l_run0 = l_run0 * f0 + stL[q0 + g] + stL[64 + q0 + g];
        l_run1 = l_run1 * f1 + stL[q0 + 8 + g] + stL[64 + q0 + 8 + g];

        // ---- PV role: D[32ch][64q] += V[32ch][64k] * P[64k][64q] ----
        if (flg[0] | flg[1] | flg[2] | flg[3]) {
            #pragma unroll
            for (int fn = 0; fn < 8; ++fn) {
                float2 ff = *(float2*)(stF + fn * 8 + 2 * t);
                #pragma unroll
                for (int fm = 0; fm < 2; ++fm) {
                    D[fm][fn][0] *= ff.x; D[fm][fn][1] *= ff.y;
                    D[fm][fn][2] *= ff.x; D[fm][fn][3] *= ff.y;
                }
            }
        }
        const char* vsm = smem + VS_OFF + buf * VS_BUF;
        #pragma unroll
        for (int ks = 0; ks < 4; ++ks) {
            uint32_t va[2][4];
            #pragma unroll
            for (int fm = 0; fm < 2; ++fm) {
                const char* vb = vsm + (ch0 + fm * 16 + g) * 144 + ks * 32 + t * 4;
                va[fm][0] = *(const uint32_t*)(vb);
                va[fm][1] = *(const uint32_t*)(vb + 8 * 144);
                va[fm][2] = *(const uint32_t*)(vb + 16);
                va[fm][3] = *(const uint32_t*)(vb + 8 * 144 + 16);
            }
            #pragma unroll
            for (int fn = 0; fn < 8; ++fn) {
                const char* pb = smem + PS_OFF + (fn * 8 + g) * 144 + ks * 32 + t * 4;
                uint32_t b0 = *(const uint32_t*)(pb);
                uint32_t b1 = *(const uint32_t*)(pb + 16);
                mma_bf16_16816(D[0][fn], va[0][0], va[0][1], va[0][2], va[0][3], b0, b1);
                mma_bf16_16816(D[1][fn], va[1][0], va[1][1], va[1][2], va[1][3], b0, b1);
            }
        }
    }

    // publish final 1/l per query
    if (khalf == 0 && t == 0) {
        inv[q0 + g] = 1.0f / l_run0;
        inv[q0 + 8 + g] = 1.0f / l_run1;
    }
    __syncthreads();

    // ---- epilogue: out[ch][m0+q] = x + D * inv[q], direct coalesced ----
    const float* xb = x + (size_t)b * CN * NN + m0;
    float* ob = out + (size_t)b * CN * NN + m0;
    #pragma unroll
    for (int fn = 0; fn < 8; ++fn) {
        int q = fn * 8 + 2 * t;
        float2 iv = *(float2*)(inv + q);
        #pragma unroll
        for (int fm = 0; fm < 2; ++fm) {
            int chv = ch0 + fm * 16 + g;
            size_t o1 = (size_t)chv * NN + q;
            float2 x1 = *(const float2*)(xb + o1);
            float2 w1;
            w1.x = x1.x + D[fm][fn][0] * iv.x;
            w1.y = x1.y + D[fm][fn][1] * iv.y;
            *(float2*)(ob + o1) = w1;
            size_t o2 = (size_t)(chv + 8) * NN + q;
            float2 x2 = *(const float2*)(xb + o2);
            float2 w2;
            w2.x = x2.x + D[fm][fn][2] * iv.x;
            w2.y = x2.y + D[fm][fn][3] * iv.y;
            *(float2*)(ob + o2) = w2;
        }
    }
}

// ---------------- launcher ----------------
extern "C" void kernel_launch(void* const* d_in, const int* in_sizes, int n_in,
                              void* d_out, int out_size) {
    const float* x  = (const float*)d_in[0];
    const float* w1 = (const float*)d_in[1];
    const float* w2 = (const float*)d_in[2];
    const float* w3 = (const float*)d_in[3];
    const float* g1 = (const float*)d_in[4];
    const float* b1 = (const float*)d_in[5];
    const float* g2 = (const float*)d_in[6];
    const float* b2 = (const float*)d_in[7];
    const float* g3 = (const float*)d_in[8];
    const float* b3 = (const float*)d_in[9];
    float* out = (float*)d_out;

    cudaFuncSetAttribute(flash_mma, cudaFuncAttributeMaxDynamicSharedMemorySize, SM_TOT);
    cudaFuncSetAttribute(qkd_mma, cudaFuncAttributeMaxDynamicSharedMemorySize, QK_SM);

    zero_kernel<<<256, 256>>>();
    convx_kernel<<<dim3(64, 4, 4), 256>>>(x);
    gram_mma<<<dim3(10, 1, 16), 256>>>(0);
    fold_kernel<<<40, 256>>>(w1, w2, w3, g1, b1, g2, b2, g3, b3);
    qkd_mma<<<dim3(5, 64), 256, QK_SM>>>(0);
    flash_mma<<<dim3(64, 4), 256, SM_TOT>>>(x, out);
}

// round 12
// speedup vs baseline: 1.0475x; 1.0475x over previous
#include <cuda_runtime.h>
#include <cuda_bf16.h>
#include <cstdint>

#define BB 4
#define CN 256
#define NN 4096
#define OTOT 320
#define BN_TOT 16384.0f
#define KTOT 16384

// ---------------- device scratch ----------------
__device__ float g_mx[CN];                            // raw channel sums
__device__ float g_G[CN * CN];
__device__ float g_Bf[OTOT];
__device__ __nv_bfloat16 g_Wh[OTOT * CN];             // folded W hi, [o][c]
__device__ __nv_bfloat16 g_Wl[OTOT * CN];             // folded W lo, [o][c]
__device__ __nv_bfloat16 g_xh[(size_t)CN * KTOT];     // x hi, [c][b*n]
__device__ __nv_bfloat16 g_xl[(size_t)CN * KTOT];     // x lo, [c][b*n]
__device__ __nv_bfloat16 g_xTh[(size_t)KTOT * CN];    // x hi, [b*n][c]
__device__ __nv_bfloat16 g_xTl[(size_t)KTOT * CN];    // x lo, [b*n][c]
__device__ __nv_bfloat16 g_Qb[(size_t)BB * NN * 128]; // [b][n][qhi32|qlo32|qhi32|0]
__device__ __nv_bfloat16 g_Kb[(size_t)BB * NN * 128]; // [b][n][khi32|khi32|klo32|0]
__device__ __nv_bfloat16 g_Vb[(size_t)BB * CN * NN];  // bf16, [b][c][n]

// ---------------- mma.sync / async helpers ----------------
__device__ __forceinline__ void mma_bf16_16816(float* c, uint32_t a0, uint32_t a1,
                                               uint32_t a2, uint32_t a3,
                                               uint32_t b0, uint32_t b1) {
    asm volatile("mma.sync.aligned.m16n8k16.row.col.f32.bf16.bf16.f32 "
        "{%0,%1,%2,%3}, {%4,%5,%6,%7}, {%8,%9}, {%0,%1,%2,%3};"
        : "+f"(c[0]), "+f"(c[1]), "+f"(c[2]), "+f"(c[3])
        : "r"(a0), "r"(a1), "r"(a2), "r"(a3), "r"(b0), "r"(b1));
}
__device__ __forceinline__ void cp16(uint32_t dst, const void* src) {
    asm volatile("cp.async.cg.shared.global [%0], [%1], 16;" :: "r"(dst), "l"(src));
}
#define CP_COMMIT() asm volatile("cp.async.commit_group;" ::: "memory")
#define CP_WAIT0()  asm volatile("cp.async.wait_group 0;" ::: "memory")
#define CP_WAIT1()  asm volatile("cp.async.wait_group 1;" ::: "memory")
__device__ __forceinline__ uint32_t smem_u32(const void* p) {
    uint32_t a;
    asm("{ .reg .u64 t; cvta.to.shared.u64 t, %1; cvt.u32.u64 %0, t; }" : "=r"(a) : "l"(p));
    return a;
}
__device__ __forceinline__ uint32_t pack_bf2(float a, float b) {
    __nv_bfloat162 h = __floats2bfloat162_rn(a, b);
    return *(uint32_t*)&h;
}

// ---------------- prologue ----------------
__global__ void zero_kernel() {
    int i = blockIdx.x * blockDim.x + threadIdx.x;
    g_G[i] = 0.0f;
    if (i < CN) g_mx[i] = 0.0f;
}

// tiled transpose/convert: x -> bf16 hi/lo in [c][bn] AND [bn][c]; fused channel sums
__global__ void convx_kernel(const float* __restrict__ x) {
    __shared__ float tile[64][65];
    int n0 = blockIdx.x * 64, c0 = blockIdx.y * 64, b = blockIdx.z;
    int tid = threadIdx.x;
    int rr = tid >> 6, jj = tid & 63;
    const float* xb = x + ((size_t)b * CN + c0) * NN + n0;
    #pragma unroll
    for (int r = 0; r < 16; ++r) {
        int i = r * 4 + rr;
        tile[i][jj] = xb[(size_t)i * NN + jj];
    }
    __syncthreads();
    if (tid < 64) {
        float s = 0.0f;
        #pragma unroll
        for (int j = 0; j < 64; ++j) s += tile[tid][j];
        atomicAdd(&g_mx[c0 + tid], s);
    }
    size_t bn0 = (size_t)b * NN + n0;
    #pragma unroll
    for (int r = 0; r < 16; ++r) {
        int i = r * 4 + rr;
        float v = tile[i][jj];
        __nv_bfloat16 hi = __float2bfloat16(v);
        __nv_bfloat16 lo = __float2bfloat16(v - __bfloat162float(hi));
        size_t off = (size_t)(c0 + i) * KTOT + bn0 + jj;
        g_xh[off] = hi; g_xl[off] = lo;
    }
    #pragma unroll
    for (int r = 0; r < 16; ++r) {
        int i = r * 4 + rr;           // n index
        float v = tile[jj][i];        // [c=jj][n=i]
        __nv_bfloat16 hi = __float2bfloat16(v);
        __nv_bfloat16 lo = __float2bfloat16(v - __bfloat162float(hi));
        size_t off = (bn0 + i) * CN + c0 + jj;
        g_xTh[off] = hi; g_xTl[off] = lo;
    }
}

// ---------------- Gram via mma.sync (hi/lo, symmetric: upper-triangle tiles only) ----------------
#define GR_STRIDE 144
#define GR_MAT (64 * GR_STRIDE)
__global__ void __launch_bounds__(256, 2)
gram_mma(int dummy) {
    __shared__ __align__(16) char smem[4 * GR_MAT];
    uint32_t sb = smem_u32(smem);
    int tid = threadIdx.x;
    int lane = tid & 31, wid = tid >> 5;
    int g = lane >> 2, t = lane & 3;
    int wm = wid >> 2, wn = wid & 3;
    // map blockIdx.x (0..9) -> upper-triangle pair (r4, c4), r4 <= c4
    int r4 = 0, rem = blockIdx.x;
    while (rem >= 4 - r4) { rem -= 4 - r4; ++r4; }
    int c4 = r4 + rem;
    int c0 = r4 * 64, c1 = c4 * 64;
    int kseg = blockIdx.z * 1024;

    float C[2][2][4] = {};

    for (int ch = 0; ch < 16; ++ch) {
        int k0 = kseg + ch * 64;
        __syncthreads();
        #pragma unroll
        for (int i = tid; i < 512; i += 256) {
            int row = i >> 3, col = i & 7;
            cp16(sb + 0 * GR_MAT + row * GR_STRIDE + col * 16,
                 g_xh + (size_t)(c0 + row) * KTOT + k0 + col * 8);
            cp16(sb + 1 * GR_MAT + row * GR_STRIDE + col * 16,
                 g_xl + (size_t)(c0 + row) * KTOT + k0 + col * 8);
            cp16(sb + 2 * GR_MAT + row * GR_STRIDE + col * 16,
                 g_xh + (size_t)(c1 + row) * KTOT + k0 + col * 8);
            cp16(sb + 3 * GR_MAT + row * GR_STRIDE + col * 16,
                 g_xl + (size_t)(c1 + row) * KTOT + k0 + col * 8);
        }
        CP_COMMIT();
        CP_WAIT0();
        __syncthreads();
        const char* Ah = smem;
        const char* Al = smem + GR_MAT;
        const char* Bh = smem + 2 * GR_MAT;
        const char* Bl = smem + 3 * GR_MAT;
        #pragma unroll
        for (int ks = 0; ks < 4; ++ks) {
            int koff = ks * 32 + t * 4;
            uint32_t ah[2][4], al[2][4];
            #pragma unroll
            for (int fm = 0; fm < 2; ++fm) {
                int r = wm * 32 + fm * 16 + g;
                ah[fm][0] = *(const uint32_t*)(Ah + r * GR_STRIDE + koff);
                ah[fm][1] = *(const uint32_t*)(Ah + (r + 8) * GR_STRIDE + koff);
                ah[fm][2] = *(const uint32_t*)(Ah + r * GR_STRIDE + koff + 16);
                ah[fm][3] = *(const uint32_t*)(Ah + (r + 8) * GR_STRIDE + koff + 16);
                al[fm][0] = *(const uint32_t*)(Al + r * GR_STRIDE + koff);
                al[fm][1] = *(const uint32_t*)(Al + (r + 8) * GR_STRIDE + koff);
                al[fm][2] = *(const uint32_t*)(Al + r * GR_STRIDE + koff + 16);
                al[fm][3] = *(const uint32_t*)(Al + (r + 8) * GR_STRIDE + koff + 16);
            }
            #pragma unroll
            for (int fn = 0; fn < 2; ++fn) {
                int r = wn * 16 + fn * 8 + g;
                uint32_t bh0 = *(const uint32_t*)(Bh + r * GR_STRIDE + koff);
                uint32_t bh1 = *(const uint32_t*)(Bh + r * GR_STRIDE + koff + 16);
                uint32_t bl0 = *(const uint32_t*)(Bl + r * GR_STRIDE + koff);
                uint32_t bl1 = *(const uint32_t*)(Bl + r * GR_STRIDE + koff + 16);
                #pragma unroll
                for (int fm = 0; fm < 2; ++fm) {
                    mma_bf16_16816(C[fm][fn], ah[fm][0], ah[fm][1], ah[fm][2], ah[fm][3], bh0, bh1);
                    mma_bf16_16816(C[fm][fn], ah[fm][0], ah[fm][1], ah[fm][2], ah[fm][3], bl0, bl1);
                    mma_bf16_16816(C[fm][fn], al[fm][0], al[fm][1], al[fm][2], al[fm][3], bh0, bh1);
                }
            }
        }
    }
    int mirror = (c0 != c1);
    #pragma unroll
    for (int fm = 0; fm < 2; ++fm) {
        #pragma unroll
        for (int fn = 0; fn < 2; ++fn) {
            int r0 = c0 + wm * 32 + fm * 16 + g;
            int cc = c1 + wn * 16 + fn * 8 + 2 * t;
            atomicAdd(&g_G[r0 * CN + cc],           C[fm][fn][0]);
            atomicAdd(&g_G[r0 * CN + cc + 1],       C[fm][fn][1]);
            atomicAdd(&g_G[(r0 + 8) * CN + cc],     C[fm][fn][2]);
            atomicAdd(&g_G[(r0 + 8) * CN + cc + 1], C[fm][fn][3]);
            if (mirror) {
                atomicAdd(&g_G[cc * CN + r0],           C[fm][fn][0]);
                atomicAdd(&g_G[(cc + 1) * CN + r0],     C[fm][fn][1]);
                atomicAdd(&g_G[cc * CN + r0 + 8],       C[fm][fn][2]);
                atomicAdd(&g_G[(cc + 1) * CN + r0 + 8], C[fm][fn][3]);
            }
        }
    }
}

// ---------------- fold BN (round-10 version: 320 blocks, ILP accumulators) ----------------
__global__ void fold_kernel(const float* __restrict__ w1, const float* __restrict__ w2,
                            const float* __restrict__ w3,
                            const float* __restrict__ g1, const float* __restrict__ b1,
                            const float* __restrict__ g2, const float* __restrict__ b2,
                            const float* __restrict__ g3, const float* __restrict__ b3) {
    int o = blockIdx.x, tid = threadIdx.x;
    const float* w; float gg, bb;
    if (o < 32)      { w = w1 + o * CN;        gg = g1[o];      bb = b1[o]; }
    else if (o < 64) { w = w2 + (o - 32) * CN; gg = g2[o - 32]; bb = b2[o - 32]; }
    else             { w = w3 + (o - 64) * CN; gg = g3[o - 64]; bb = b3[o - 64]; }
    __shared__ float ws[256], redE[256], redM[256], sc_sh;
    ws[tid] = w[tid]; __syncthreads();
    float a0 = 0.0f, a1 = 0.0f, a2 = 0.0f, a3 = 0.0f;
    #pragma unroll 8
    for (int c = 0; c < CN; c += 4) {
        a0 += g_G[(c + 0) * CN + tid] * ws[c + 0];
        a1 += g_G[(c + 1) * CN + tid] * ws[c + 1];
        a2 += g_G[(c + 2) * CN + tid] * ws[c + 2];
        a3 += g_G[(c + 3) * CN + tid] * ws[c + 3];
    }
    redE[tid] = (a0 + a1 + a2 + a3) * ws[tid];
    redM[tid] = ws[tid] * g_mx[tid] * (1.0f / BN_TOT);
    __syncthreads();
    for (int st = 128; st > 0; st >>= 1) {
        if (tid < st) { redE[tid] += redE[tid + st]; redM[tid] += redM[tid + st]; }
        __syncthreads();
    }
    if (tid == 0) {
        float m = redM[0], E = redE[0] * (1.0f / BN_TOT);
        float rs = rsqrtf(E - m * m + 1e-5f);
        float sc = gg * rs;
        sc_sh = sc;
        g_Bf[o] = bb - sc * m;
    }
    __syncthreads();
    float wf = sc_sh * ws[tid];
    __nv_bfloat16 hi = __float2bfloat16(wf);
    __nv_bfloat16 lo = __float2bfloat16(wf - __bfloat162float(hi));
    g_Wh[o * CN + tid] = hi;
    g_Wl[o * CN + tid] = lo;
}

// ---------------- qkd via mma.sync: Z[o][bn] = relu(W x + b) -> Qb/Kb/Vb ----------------
#define QK_SM 92160
__global__ void __launch_bounds__(256, 2)
qkd_mma(int dummy) {
    extern __shared__ __align__(16) char smem[];
    uint32_t sb = smem_u32(smem);
    int tid = threadIdx.x;
    int lane = tid & 31, wid = tid >> 5;
    int g = lane >> 2, t = lane & 3;
    int wm = wid >> 2, wn = wid & 3;
    int o0 = blockIdx.x * 64;
    int bn0 = blockIdx.y * 256;

    float C[2][8][4] = {};

    for (int kc = 0; kc < 4; ++kc) {
        int k0 = kc * 64;
        __syncthreads();
        #pragma unroll
        for (int i = tid; i < 512; i += 256) {
            int row = i >> 3, col = i & 7;
            cp16(sb + row * 144 + col * 16,        g_Wh + (size_t)(o0 + row) * CN + k0 + col * 8);
            cp16(sb + 9216 + row * 144 + col * 16, g_Wl + (size_t)(o0 + row) * CN + k0 + col * 8);
        }
        #pragma unroll
        for (int i = tid; i < 2048; i += 256) {
            int row = i >> 3, col = i & 7;
            cp16(sb + 18432 + row * 144 + col * 16, g_xTh + (bn0 + row) * (size_t)CN + k0 + col * 8);
            cp16(sb + 55296 + row * 144 + col * 16, g_xTl + (bn0 + row) * (size_t)CN + k0 + col * 8);
        }
        CP_COMMIT();
        CP_WAIT0();
        __syncthreads();
        const char* Wh = smem;
        const char* Wl = smem + 9216;
        const char* Xh = smem + 18432;
        const char* Xl = smem + 55296;
        #pragma unroll
        for (int ks = 0; ks < 4; ++ks) {
            int koff = ks * 32 + t * 4;
            uint32_t ah[2][4], al[2][4];
            #pragma unroll
            for (int fm = 0; fm < 2; ++fm) {
                int r = wm * 32 + fm * 16 + g;
                ah[fm][0] = *(const uint32_t*)(Wh + r * 144 + koff);
                ah[fm][1] = *(const uint32_t*)(Wh + (r + 8) * 144 + koff);
                ah[fm][2] = *(const uint32_t*)(Wh + r * 144 + koff + 16);
                ah[fm][3] = *(const uint32_t*)(Wh + (r + 8) * 144 + koff + 16);
                al[fm][0] = *(const uint32_t*)(Wl + r * 144 + koff);
                al[fm][1] = *(const uint32_t*)(Wl + (r + 8) * 144 + koff);
                al[fm][2] = *(const uint32_t*)(Wl + r * 144 + koff + 16);
                al[fm][3] = *(const uint32_t*)(Wl + (r + 8) * 144 + koff + 16);
            }
            #pragma unroll
            for (int fn = 0; fn < 8; ++fn) {
                int r = wn * 64 + fn * 8 + g;
                uint32_t bh0 = *(const uint32_t*)(Xh + r * 144 + koff);
                uint32_t bh1 = *(const uint32_t*)(Xh + r * 144 + koff + 16);
                uint32_t bl0 = *(const uint32_t*)(Xl + r * 144 + koff);
                uint32_t bl1 = *(const uint32_t*)(Xl + r * 144 + koff + 16);
                #pragma unroll
                for (int fm = 0; fm < 2; ++fm) {
                    mma_bf16_16816(C[fm][fn], ah[fm][0], ah[fm][1], ah[fm][2], ah[fm][3], bh0, bh1);
                    mma_bf16_16816(C[fm][fn], ah[fm][0], ah[fm][1], ah[fm][2], ah[fm][3], bl0, bl1);
                    mma_bf16_16816(C[fm][fn], al[fm][0], al[fm][1], al[fm][2], al[fm][3], bh0, bh1);
                }
            }
        }
    }

    __nv_bfloat16 zero = __float2bfloat16(0.0f);
    #pragma unroll
    for (int fm = 0; fm < 2; ++fm) {
        int obase = o0 + wm * 32 + fm * 16 + g;
        float bias0 = g_Bf[obase], bias1 = g_Bf[obase + 8];
        #pragma unroll
        for (int fn = 0; fn < 8; ++fn) {
            int bncol = bn0 + wn * 64 + fn * 8 + 2 * t;
            int b = bncol >> 12, n = bncol & 4095;
            #pragma unroll
            for (int rr = 0; rr < 2; ++rr) {
                int o = obase + rr * 8;
                float v0 = fmaxf(C[fm][fn][rr * 2 + 0] + (rr ? bias1 : bias0), 0.0f);
                float v1 = fmaxf(C[fm][fn][rr * 2 + 1] + (rr ? bias1 : bias0), 0.0f);
                if (o >= 64) {
                    *(uint32_t*)(g_Vb + ((size_t)b * CN + (o - 64)) * NN + n) = pack_bf2(v0, v1);
                } else {
                    #pragma unroll
                    for (int e = 0; e < 2; ++e) {
                        float v = e ? v1 : v0;
                        __nv_bfloat16 hi = __float2bfloat16(v);
                        __nv_bfloat16 lo = __float2bfloat16(v - __bfloat162float(hi));
                        size_t base = ((size_t)b * NN + n + e) * 128;
                        if (o < 32) {
                            g_Qb[base + o] = hi; g_Qb[base + 32 + o] = lo;
                            g_Qb[base + 64 + o] = hi; g_Qb[base + 96 + o] = zero;
                        } else {
                            int oc = o - 32;
                            g_Kb[base + oc] = hi; g_Kb[base + 32 + oc] = hi;
                            g_Kb[base + 64 + oc] = lo; g_Kb[base + 96 + oc] = zero;
                        }
                    }
                }
            }
        }
    }
}

// ---------------- flash attention: channel-major PV, NT=64 (round-10 pipeline) ----------------
#define KS_OFF 0
#define KS_BUF 13312
#define VS_OFF 26624
#define VS_BUF 36864
#define PS_OFF 100352
#define STM_OFF 109568
#define STL_OFF 110080
#define STF_OFF 110592
#define FLG_OFF 110848
#define INV_OFF 110864
#define SM_TOT 111616

__global__ void __launch_bounds__(256, 2)
flash_mma(const float* __restrict__ x, float* __restrict__ out) {
    extern __shared__ __align__(16) char smem[];
    uint32_t sb = smem_u32(smem);
    int tid = threadIdx.x;
    int lane = tid & 31, wid = tid >> 5;
    int g = lane >> 2, t = lane & 3;
    int mrow = wid & 3, khalf = wid >> 2;
    int q0 = mrow * 16;
    int ch0 = wid * 32;
    int b = blockIdx.y, m0 = blockIdx.x * 64;

    float* stM = (float*)(smem + STM_OFF);
    float* stL = (float*)(smem + STL_OFF);
    float* stF = (float*)(smem + STF_OFF);
    uint32_t* flg = (uint32_t*)(smem + FLG_OFF);
    float* inv = (float*)(smem + INV_OFF);

    uint32_t qa[6][4];
    {
        const __nv_bfloat16* qr0 = g_Qb + ((size_t)b * NN + m0 + q0 + g) * 128;
        const __nv_bfloat16* qr1 = qr0 + (size_t)8 * 128;
        #pragma unroll
        for (int ks = 0; ks < 6; ++ks) {
            int e = ks * 16 + 2 * t;
            qa[ks][0] = *(const uint32_t*)(qr0 + e);
            qa[ks][1] = *(const uint32_t*)(qr1 + e);
            qa[ks][2] = *(const uint32_t*)(qr0 + e + 8);
            qa[ks][3] = *(const uint32_t*)(qr1 + e + 8);
        }
    }

    const char* kgb = (const char*)(g_Kb + ((size_t)b * NN) * 128);
    const char* vgb = (const char*)(g_Vb + (size_t)b * CN * NN);

    // prefetch chunk 0 into buf 0 (K: 64 rows x 12 cp16 = 192B data; V: 256 rows x 8 cp16)
    {
        #pragma unroll
        for (int i = tid; i < 768; i += 256) {
            int row = i / 12, col = i - row * 12;
            cp16(sb + KS_OFF + row * 208 + col * 16, kgb + (size_t)row * 256 + col * 16);
        }
        #pragma unroll
        for (int i = tid; i < 2048; i += 256) {
            int c = i >> 3, j = i & 7;
            cp16(sb + VS_OFF + c * 144 + j * 16, vgb + (size_t)c * (NN * 2) + j * 16);
        }
        CP_COMMIT();
    }

    float D[2][8][4];
    #pragma unroll
    for (int fm = 0; fm < 2; ++fm)
        #pragma unroll
        for (int fn = 0; fn < 8; ++fn) { D[fm][fn][0] = D[fm][fn][1] = D[fm][fn][2] = D[fm][fn][3] = 0.0f; }
    float m_run0 = -1e30f, m_run1 = -1e30f, l_run0 = 0.0f, l_run1 = 0.0f;

    for (int ch = 0; ch < 64; ++ch) {
        int buf = ch & 1;
        __syncthreads();   // B1: all consumers done with buf^1 + Ps/stF
        if (ch + 1 < 64) {
            int n1 = (ch + 1) * 64;
            uint32_t kd = sb + KS_OFF + (buf ^ 1) * KS_BUF;
            uint32_t vd = sb + VS_OFF + (buf ^ 1) * VS_BUF;
            #pragma unroll
            for (int i = tid; i < 768; i += 256) {
                int row = i / 12, col = i - row * 12;
                cp16(kd + row * 208 + col * 16, kgb + (size_t)(n1 + row) * 256 + col * 16);
            }
            #pragma unroll
            for (int i = tid; i < 2048; i += 256) {
                int c = i >> 3, j = i & 7;
                cp16(vd + c * 144 + j * 16, vgb + (size_t)c * (NN * 2) + (size_t)n1 * 2 + j * 16);
            }
        }
        CP_COMMIT();
        CP_WAIT1();
        __syncthreads();   // B2: buf data visible

        // ---- score role: s[16q][32k] (keys khalf*32..+32) ----
        const char* ksm = smem + KS_OFF + buf * KS_BUF;
        float sc[4][4] = {};
        #pragma unroll
        for (int ks = 0; ks < 6; ++ks) {
            #pragma unroll
            for (int nt = 0; nt < 4; ++nt) {
                const char* kbase = ksm + (khalf * 32 + nt * 8 + g) * 208 + ks * 32 + t * 4;
                uint32_t b0 = *(const uint32_t*)(kbase);
                uint32_t b1 = *(const uint32_t*)(kbase + 16);
                mma_bf16_16816(sc[nt], qa[ks][0], qa[ks][1], qa[ks][2], qa[ks][3], b0, b1);
            }
        }
        float mp0 = fmaxf(fmaxf(sc[0][0], sc[0][1]), fmaxf(sc[1][0], sc[1][1]));
        mp0 = fmaxf(mp0, fmaxf(fmaxf(sc[2][0], sc[2][1]), fmaxf(sc[3][0], sc[3][1])));
        float mp1 = fmaxf(fmaxf(sc[0][2], sc[0][3]), fmaxf(sc[1][2], sc[1][3]));
        mp1 = fmaxf(mp1, fmaxf(fmaxf(sc[2][2], sc[2][3]), fmaxf(sc[3][2], sc[3][3])));
        mp0 = fmaxf(mp0, __shfl_xor_sync(0xffffffffu, mp0, 1));
        mp0 = fmaxf(mp0, __shfl_xor_sync(0xffffffffu, mp0, 2));
        mp1 = fmaxf(mp1, __shfl_xor_sync(0xffffffffu, mp1, 1));
        mp1 = fmaxf(mp1, __shfl_xor_sync(0xffffffffu, mp1, 2));
        if (t == 0) {
            stM[khalf * 64 + q0 + g] = mp0;
            stM[khalf * 64 + q0 + 8 + g] = mp1;
        }
        __syncthreads();   // B3: stM visible
        float mt0 = fmaxf(stM[q0 + g], stM[64 + q0 + g]);
        float mt1 = fmaxf(stM[q0 + 8 + g], stM[64 + q0 + 8 + g]);
        float mn0 = fmaxf(m_run0, mt0), mn1 = fmaxf(m_run1, mt1);
        float f0 = __expf(m_run0 - mn0), f1 = __expf(m_run1 - mn1);
        m_run0 = mn0; m_run1 = mn1;

        float ls0 = 0.0f, ls1 = 0.0f;
        #pragma unroll
        for (int nt = 0; nt < 4; ++nt) {
            float e0 = __expf(sc[nt][0] - mn0);
            float e1 = __expf(sc[nt][1] - mn0);
            float e2 = __expf(sc[nt][2] - mn1);
            float e3 = __expf(sc[nt][3] - mn1);
            ls0 += e0 + e1; ls1 += e2 + e3;
            char* pr0 = smem + PS_OFF + (q0 + g) * 144 + khalf * 64 + nt * 16 + t * 4;
            char* pr1 = smem + PS_OFF + (q0 + 8 + g) * 144 + khalf * 64 + nt * 16 + t * 4;
            *(uint32_t*)(pr0) = pack_bf2(e0, e1);
            *(uint32_t*)(pr1) = pack_bf2(e2, e3);
        }
        uint32_t nb = __ballot_sync(0xffffffffu, (f0 < 1.0f) || (f1 < 1.0f));
        if (khalf == 0 && t == 0) {
            stF[q0 + g] = f0;
            stF[q0 + 8 + g] = f1;
        }
        if (khalf == 0 && lane == 0) flg[mrow] = nb;
        ls0 += __shfl_xor_sync(0xffffffffu, ls0, 1);
        ls0 += __shfl_xor_sync(0xffffffffu, ls0, 2);
        ls1 += __shfl_xor_sync(0xffffffffu, ls1, 1);
        ls1 += __shfl_xor_sync(0xffffffffu, ls1, 2);
        if (t == 0) {
            stL[khalf * 64 + q0 + g] = ls0;
            stL[khalf * 64 + q0 + 8 + g] = ls1;
        }
        __syncthreads();   // B4: Ps both halves + stL + stF + flags visible
        l_run0 = l_run0 * f0 + stL[q0 + g] + stL[64 + q0 + g];
        l_run1 = l_run1 * f1 + stL[q0 + 8 + g] + stL[64 + q0 + 8 + g];

        // ---- PV role: D[32ch][64q] += V[32ch][64k] * P[64k][64q] ----
        if (flg[0] | flg[1] | flg[2] | flg[3]) {
            #pragma unroll
            for (int fn = 0; fn < 8; ++fn) {
                float2 ff = *(float2*)(stF + fn * 8 + 2 * t);
                #pragma unroll
                for (int fm = 0; fm < 2; ++fm) {
                    D[fm][fn][0] *= ff.x; D[fm][fn][1] *= ff.y;
                    D[fm][fn][2] *= ff.x; D[fm][fn][3] *= ff.y;
                }
            }
        }
        const char* vsm = smem + VS_OFF + buf * VS_BUF;
        #pragma unroll
        for (int ks = 0; ks < 4; ++ks) {
            uint32_t va[2][4];
            #pragma unroll
            for (int fm = 0; fm < 2; ++fm) {
                const char* vb = vsm + (ch0 + fm * 16 + g) * 144 + ks * 32 + t * 4;
                va[fm][0] = *(const uint32_t*)(vb);
                va[fm][1] = *(const uint32_t*)(vb + 8 * 144);
                va[fm][2] = *(const uint32_t*)(vb + 16);
                va[fm][3] = *(const uint32_t*)(vb + 8 * 144 + 16);
            }
            #pragma unroll
            for (int fn = 0; fn < 8; ++fn) {
                const char* pb = smem + PS_OFF + (fn * 8 + g) * 144 + ks * 32 + t * 4;
                uint32_t b0 = *(const uint32_t*)(pb);
                uint32_t b1 = *(const uint32_t*)(pb + 16);
                mma_bf16_16816(D[0][fn], va[0][0], va[0][1], va[0][2], va[0][3], b0, b1);
                mma_bf16_16816(D[1][fn], va[1][0], va[1][1], va[1][2], va[1][3], b0, b1);
            }
        }
    }

    // publish final 1/l per query
    if (khalf == 0 && t == 0) {
        inv[q0 + g] = 1.0f / l_run0;
        inv[q0 + 8 + g] = 1.0f / l_run1;
    }
    __syncthreads();

    // ---- epilogue: out[ch][m0+q] = x + D * inv[q], direct coalesced ----
    const float* xb = x + (size_t)b * CN * NN + m0;
    float* ob = out + (size_t)b * CN * NN + m0;
    #pragma unroll
    for (int fn = 0; fn < 8; ++fn) {
        int q = fn * 8 + 2 * t;
        float2 iv = *(float2*)(inv + q);
        #pragma unroll
        for (int fm = 0; fm < 2; ++fm) {
            int chv = ch0 + fm * 16 + g;
            size_t o1 = (size_t)chv * NN + q;
            float2 x1 = *(const float2*)(xb + o1);
            float2 w1;
            w1.x = x1.x + D[fm][fn][0] * iv.x;
            w1.y = x1.y + D[fm][fn][1] * iv.y;
            *(float2*)(ob + o1) = w1;
            size_t o2 = (size_t)(chv + 8) * NN + q;
            float2 x2 = *(const float2*)(xb + o2);
            float2 w2;
            w2.x = x2.x + D[fm][fn][2] * iv.x;
            w2.y = x2.y + D[fm][fn][3] * iv.y;
            *(float2*)(ob + o2) = w2;
        }
    }
}

// ---------------- launcher ----------------
extern "C" void kernel_launch(void* const* d_in, const int* in_sizes, int n_in,
                              void* d_out, int out_size) {
    const float* x  = (const float*)d_in[0];
    const float* w1 = (const float*)d_in[1];
    const float* w2 = (const float*)d_in[2];
    const float* w3 = (const float*)d_in[3];
    const float* g1 = (const float*)d_in[4];
    const float* b1 = (const float*)d_in[5];
    const float* g2 = (const float*)d_in[6];
    const float* b2 = (const float*)d_in[7];
    const float* g3 = (const float*)d_in[8];
    const float* b3 = (const float*)d_in[9];
    float* out = (float*)d_out;

    cudaFuncSetAttribute(flash_mma, cudaFuncAttributeMaxDynamicSharedMemorySize, SM_TOT);
    cudaFuncSetAttribute(qkd_mma, cudaFuncAttributeMaxDynamicSharedMemorySize, QK_SM);

    zero_kernel<<<256, 256>>>();
    convx_kernel<<<dim3(64, 4, 4), 256>>>(x);
    gram_mma<<<dim3(10, 1, 16), 256>>>(0);
    fold_kernel<<<320, 256>>>(w1, w2, w3, g1, b1, g2, b2, g3, b3);
    qkd_mma<<<dim3(5, 64), 256, QK_SM>>>(0);
    flash_mma<<<dim3(64, 4), 256, SM_TOT>>>(x, out);
}

// round 14
// speedup vs baseline: 1.1557x; 1.1033x over previous
#include <cuda_runtime.h>
#include <cuda_bf16.h>
#include <cstdint>

#define BB 4
#define CN 256
#define NN 4096
#define OTOT 320
#define BN_TOT 16384.0f
#define KTOT 16384

// ---------------- device scratch ----------------
__device__ float g_mx[CN];                            // raw channel sums
__device__ float g_G[CN * CN];
__device__ float g_Bf[OTOT];
__device__ __nv_bfloat16 g_Wh[OTOT * CN];             // folded W hi, [o][c]
__device__ __nv_bfloat16 g_Wl[OTOT * CN];             // folded W lo, [o][c]
__device__ __nv_bfloat16 g_xh[(size_t)CN * KTOT];     // x hi, [c][b*n]
__device__ __nv_bfloat16 g_xl[(size_t)CN * KTOT];     // x lo, [c][b*n]
__device__ __nv_bfloat16 g_xTh[(size_t)KTOT * CN];    // x hi, [b*n][c]
__device__ __nv_bfloat16 g_xTl[(size_t)KTOT * CN];    // x lo, [b*n][c]
__device__ __nv_bfloat16 g_Qb[(size_t)BB * NN * 128]; // [b][n][qhi32|qlo32|qhi32|0]
__device__ __nv_bfloat16 g_Kb[(size_t)BB * NN * 128]; // [b][n][khi32|khi32|klo32|0]
__device__ __nv_bfloat16 g_Vb[(size_t)BB * CN * NN];  // bf16, [b][c][n]

// ---------------- mma.sync / async helpers ----------------
__device__ __forceinline__ void mma_bf16_16816(float* c, uint32_t a0, uint32_t a1,
                                               uint32_t a2, uint32_t a3,
                                               uint32_t b0, uint32_t b1) {
    asm volatile("mma.sync.aligned.m16n8k16.row.col.f32.bf16.bf16.f32 "
        "{%0,%1,%2,%3}, {%4,%5,%6,%7}, {%8,%9}, {%0,%1,%2,%3};"
        : "+f"(c[0]), "+f"(c[1]), "+f"(c[2]), "+f"(c[3])
        : "r"(a0), "r"(a1), "r"(a2), "r"(a3), "r"(b0), "r"(b1));
}
__device__ __forceinline__ void ldsm4(uint32_t& r0, uint32_t& r1, uint32_t& r2, uint32_t& r3,
                                      uint32_t a) {
    asm volatile("ldmatrix.sync.aligned.m8n8.x4.shared.b16 {%0,%1,%2,%3}, [%4];"
        : "=r"(r0), "=r"(r1), "=r"(r2), "=r"(r3) : "r"(a));
}
__device__ __forceinline__ void cp16(uint32_t dst, const void* src) {
    asm volatile("cp.async.cg.shared.global [%0], [%1], 16;" :: "r"(dst), "l"(src));
}
#define CP_COMMIT() asm volatile("cp.async.commit_group;" ::: "memory")
#define CP_WAIT0()  asm volatile("cp.async.wait_group 0;" ::: "memory")
#define CP_WAIT1()  asm volatile("cp.async.wait_group 1;" ::: "memory")
__device__ __forceinline__ uint32_t smem_u32(const void* p) {
    uint32_t a;
    asm("{ .reg .u64 t; cvta.to.shared.u64 t, %1; cvt.u32.u64 %0, t; }" : "=r"(a) : "l"(p));
    return a;
}
__device__ __forceinline__ uint32_t pack_bf2(float a, float b) {
    __nv_bfloat162 h = __floats2bfloat162_rn(a, b);
    return *(uint32_t*)&h;
}

// ---------------- prologue ----------------
__global__ void zero_kernel() {
    int i = blockIdx.x * blockDim.x + threadIdx.x;
    g_G[i] = 0.0f;
    if (i < CN) g_mx[i] = 0.0f;
}

// tiled transpose/convert: x -> bf16 hi/lo in [c][bn] AND [bn][c]; fused channel sums
__global__ void convx_kernel(const float* __restrict__ x) {
    __shared__ float tile[64][65];
    int n0 = blockIdx.x * 64, c0 = blockIdx.y * 64, b = blockIdx.z;
    int tid = threadIdx.x;
    int rr = tid >> 6, jj = tid & 63;
    const float* xb = x + ((size_t)b * CN + c0) * NN + n0;
    #pragma unroll
    for (int r = 0; r < 16; ++r) {
        int i = r * 4 + rr;
        tile[i][jj] = xb[(size_t)i * NN + jj];
    }
    __syncthreads();
    if (tid < 64) {
        float s = 0.0f;
        #pragma unroll
        for (int j = 0; j < 64; ++j) s += tile[tid][j];
        atomicAdd(&g_mx[c0 + tid], s);
    }
    size_t bn0 = (size_t)b * NN + n0;
    #pragma unroll
    for (int r = 0; r < 16; ++r) {
        int i = r * 4 + rr;
        float v = tile[i][jj];
        __nv_bfloat16 hi = __float2bfloat16(v);
        __nv_bfloat16 lo = __float2bfloat16(v - __bfloat162float(hi));
        size_t off = (size_t)(c0 + i) * KTOT + bn0 + jj;
        g_xh[off] = hi; g_xl[off] = lo;
    }
    #pragma unroll
    for (int r = 0; r < 16; ++r) {
        int i = r * 4 + rr;           // n index
        float v = tile[jj][i];        // [c=jj][n=i]
        __nv_bfloat16 hi = __float2bfloat16(v);
        __nv_bfloat16 lo = __float2bfloat16(v - __bfloat162float(hi));
        size_t off = (bn0 + i) * CN + c0 + jj;
        g_xTh[off] = hi; g_xTl[off] = lo;
    }
}

// ---------------- Gram via mma.sync (hi/lo, symmetric: upper-triangle tiles only) ----------------
#define GR_STRIDE 144
#define GR_MAT (64 * GR_STRIDE)
__global__ void __launch_bounds__(256, 2)
gram_mma(int dummy) {
    __shared__ __align__(16) char smem[4 * GR_MAT];
    uint32_t sb = smem_u32(smem);
    int tid = threadIdx.x;
    int lane = tid & 31, wid = tid >> 5;
    int g = lane >> 2, t = lane & 3;
    int wm = wid >> 2, wn = wid & 3;
    int r4 = 0, rem = blockIdx.x;
    while (rem >= 4 - r4) { rem -= 4 - r4; ++r4; }
    int c4 = r4 + rem;
    int c0 = r4 * 64, c1 = c4 * 64;
    int kseg = blockIdx.z * 1024;

    float C[2][2][4] = {};

    for (int ch = 0; ch < 16; ++ch) {
        int k0 = kseg + ch * 64;
        __syncthreads();
        #pragma unroll
        for (int i = tid; i < 512; i += 256) {
            int row = i >> 3, col = i & 7;
            cp16(sb + 0 * GR_MAT + row * GR_STRIDE + col * 16,
                 g_xh + (size_t)(c0 + row) * KTOT + k0 + col * 8);
            cp16(sb + 1 * GR_MAT + row * GR_STRIDE + col * 16,
                 g_xl + (size_t)(c0 + row) * KTOT + k0 + col * 8);
            cp16(sb + 2 * GR_MAT + row * GR_STRIDE + col * 16,
                 g_xh + (size_t)(c1 + row) * KTOT + k0 + col * 8);
            cp16(sb + 3 * GR_MAT + row * GR_STRIDE + col * 16,
                 g_xl + (size_t)(c1 + row) * KTOT + k0 + col * 8);
        }
        CP_COMMIT();
        CP_WAIT0();
        __syncthreads();
        const char* Ah = smem;
        const char* Al = smem + GR_MAT;
        const char* Bh = smem + 2 * GR_MAT;
        const char* Bl = smem + 3 * GR_MAT;
        #pragma unroll
        for (int ks = 0; ks < 4; ++ks) {
            int koff = ks * 32 + t * 4;
            uint32_t ah[2][4], al[2][4];
            #pragma unroll
            for (int fm = 0; fm < 2; ++fm) {
                int r = wm * 32 + fm * 16 + g;
                ah[fm][0] = *(const uint32_t*)(Ah + r * GR_STRIDE + koff);
                ah[fm][1] = *(const uint32_t*)(Ah + (r + 8) * GR_STRIDE + koff);
                ah[fm][2] = *(const uint32_t*)(Ah + r * GR_STRIDE + koff + 16);
                ah[fm][3] = *(const uint32_t*)(Ah + (r + 8) * GR_STRIDE + koff + 16);
                al[fm][0] = *(const uint32_t*)(Al + r * GR_STRIDE + koff);
                al[fm][1] = *(const uint32_t*)(Al + (r + 8) * GR_STRIDE + koff);
                al[fm][2] = *(const uint32_t*)(Al + r * GR_STRIDE + koff + 16);
                al[fm][3] = *(const uint32_t*)(Al + (r + 8) * GR_STRIDE + koff + 16);
            }
            #pragma unroll
            for (int fn = 0; fn < 2; ++fn) {
                int r = wn * 16 + fn * 8 + g;
                uint32_t bh0 = *(const uint32_t*)(Bh + r * GR_STRIDE + koff);
                uint32_t bh1 = *(const uint32_t*)(Bh + r * GR_STRIDE + koff + 16);
                uint32_t bl0 = *(const uint32_t*)(Bl + r * GR_STRIDE + koff);
                uint32_t bl1 = *(const uint32_t*)(Bl + r * GR_STRIDE + koff + 16);
                #pragma unroll
                for (int fm = 0; fm < 2; ++fm) {
                    mma_bf16_16816(C[fm][fn], ah[fm][0], ah[fm][1], ah[fm][2], ah[fm][3], bh0, bh1);
                    mma_bf16_16816(C[fm][fn], ah[fm][0], ah[fm][1], ah[fm][2], ah[fm][3], bl0, bl1);
                    mma_bf16_16816(C[fm][fn], al[fm][0], al[fm][1], al[fm][2], al[fm][3], bh0, bh1);
                }
            }
        }
    }
    int mirror = (c0 != c1);
    #pragma unroll
    for (int fm = 0; fm < 2; ++fm) {
        #pragma unroll
        for (int fn = 0; fn < 2; ++fn) {
            int r0 = c0 + wm * 32 + fm * 16 + g;
            int cc = c1 + wn * 16 + fn * 8 + 2 * t;
            atomicAdd(&g_G[r0 * CN + cc],           C[fm][fn][0]);
            atomicAdd(&g_G[r0 * CN + cc + 1],       C[fm][fn][1]);
            atomicAdd(&g_G[(r0 + 8) * CN + cc],     C[fm][fn][2]);
            atomicAdd(&g_G[(r0 + 8) * CN + cc + 1], C[fm][fn][3]);
            if (mirror) {
                atomicAdd(&g_G[cc * CN + r0],           C[fm][fn][0]);
                atomicAdd(&g_G[(cc + 1) * CN + r0],     C[fm][fn][1]);
                atomicAdd(&g_G[cc * CN + r0 + 8],       C[fm][fn][2]);
                atomicAdd(&g_G[(cc + 1) * CN + r0 + 8], C[fm][fn][3]);
            }
        }
    }
}

// ---------------- fold BN (320 blocks, ILP accumulators) ----------------
__global__ void fold_kernel(const float* __restrict__ w1, const float* __restrict__ w2,
                            const float* __restrict__ w3,
                            const float* __restrict__ g1, const float* __restrict__ b1,
                            const float* __restrict__ g2, const float* __restrict__ b2,
                            const float* __restrict__ g3, const float* __restrict__ b3) {
    int o = blockIdx.x, tid = threadIdx.x;
    const float* w; float gg, bb;
    if (o < 32)      { w = w1 + o * CN;        gg = g1[o];      bb = b1[o]; }
    else if (o < 64) { w = w2 + (o - 32) * CN; gg = g2[o - 32]; bb = b2[o - 32]; }
    else             { w = w3 + (o - 64) * CN; gg = g3[o - 64]; bb = b3[o - 64]; }
    __shared__ float ws[256], redE[256], redM[256], sc_sh;
    ws[tid] = w[tid]; __syncthreads();
    float a0 = 0.0f, a1 = 0.0f, a2 = 0.0f, a3 = 0.0f;
    #pragma unroll 8
    for (int c = 0; c < CN; c += 4) {
        a0 += g_G[(c + 0) * CN + tid] * ws[c + 0];
        a1 += g_G[(c + 1) * CN + tid] * ws[c + 1];
        a2 += g_G[(c + 2) * CN + tid] * ws[c + 2];
        a3 += g_G[(c + 3) * CN + tid] * ws[c + 3];
    }
    redE[tid] = (a0 + a1 + a2 + a3) * ws[tid];
    redM[tid] = ws[tid] * g_mx[tid] * (1.0f / BN_TOT);
    __syncthreads();
    for (int st = 128; st > 0; st >>= 1) {
        if (tid < st) { redE[tid] += redE[tid + st]; redM[tid] += redM[tid + st]; }
        __syncthreads();
    }
    if (tid == 0) {
        float m = redM[0], E = redE[0] * (1.0f / BN_TOT);
        float rs = rsqrtf(E - m * m + 1e-5f);
        float sc = gg * rs;
        sc_sh = sc;
        g_Bf[o] = bb - sc * m;
    }
    __syncthreads();
    float wf = sc_sh * ws[tid];
    __nv_bfloat16 hi = __float2bfloat16(wf);
    __nv_bfloat16 lo = __float2bfloat16(wf - __bfloat162float(hi));
    g_Wh[o * CN + tid] = hi;
    g_Wl[o * CN + tid] = lo;
}

// ---------------- qkd via mma.sync: Z[o][bn] = relu(W x + b) -> Qb/Kb/Vb ----------------
#define QK_SM 92160
__global__ void __launch_bounds__(256, 2)
qkd_mma(int dummy) {
    extern __shared__ __align__(16) char smem[];
    uint32_t sb = smem_u32(smem);
    int tid = threadIdx.x;
    int lane = tid & 31, wid = tid >> 5;
    int g = lane >> 2, t = lane & 3;
    int wm = wid >> 2, wn = wid & 3;
    int o0 = blockIdx.x * 64;
    int bn0 = blockIdx.y * 256;

    float C[2][8][4] = {};

    for (int kc = 0; kc < 4; ++kc) {
        int k0 = kc * 64;
        __syncthreads();
        #pragma unroll
        for (int i = tid; i < 512; i += 256) {
            int row = i >> 3, col = i & 7;
            cp16(sb + row * 144 + col * 16,        g_Wh + (size_t)(o0 + row) * CN + k0 + col * 8);
            cp16(sb + 9216 + row * 144 + col * 16, g_Wl + (size_t)(o0 + row) * CN + k0 + col * 8);
        }
        #pragma unroll
        for (int i = tid; i < 2048; i += 256) {
            int row = i >> 3, col = i & 7;
            cp16(sb + 18432 + row * 144 + col * 16, g_xTh + (bn0 + row) * (size_t)CN + k0 + col * 8);
            cp16(sb + 55296 + row * 144 + col * 16, g_xTl + (bn0 + row) * (size_t)CN + k0 + col * 8);
        }
        CP_COMMIT();
        CP_WAIT0();
        __syncthreads();
        const char* Wh = smem;
        const char* Wl = smem + 9216;
        const char* Xh = smem + 18432;
        const char* Xl = smem + 55296;
        #pragma unroll
        for (int ks = 0; ks < 4; ++ks) {
            int koff = ks * 32 + t * 4;
            uint32_t ah[2][4], al[2][4];
            #pragma unroll
            for (int fm = 0; fm < 2; ++fm) {
                int r = wm * 32 + fm * 16 + g;
                ah[fm][0] = *(const uint32_t*)(Wh + r * 144 + koff);
                ah[fm][1] = *(const uint32_t*)(Wh + (r + 8) * 144 + koff);
                ah[fm][2] = *(const uint32_t*)(Wh + r * 144 + koff + 16);
                ah[fm][3] = *(const uint32_t*)(Wh + (r + 8) * 144 + koff + 16);
                al[fm][0] = *(const uint32_t*)(Wl + r * 144 + koff);
                al[fm][1] = *(const uint32_t*)(Wl + (r + 8) * 144 + koff);
                al[fm][2] = *(const uint32_t*)(Wl + r * 144 + koff + 16);
                al[fm][3] = *(const uint32_t*)(Wl + (r + 8) * 144 + koff + 16);
            }
            #pragma unroll
            for (int fn = 0; fn < 8; ++fn) {
                int r = wn * 64 + fn * 8 + g;
                uint32_t bh0 = *(const uint32_t*)(Xh + r * 144 + koff);
                uint32_t bh1 = *(const uint32_t*)(Xh + r * 144 + koff + 16);
                uint32_t bl0 = *(const uint32_t*)(Xl + r * 144 + koff);
                uint32_t bl1 = *(const uint32_t*)(Xl + r * 144 + koff + 16);
                #pragma unroll
                for (int fm = 0; fm < 2; ++fm) {
                    mma_bf16_16816(C[fm][fn], ah[fm][0], ah[fm][1], ah[fm][2], ah[fm][3], bh0, bh1);
                    mma_bf16_16816(C[fm][fn], ah[fm][0], ah[fm][1], ah[fm][2], ah[fm][3], bl0, bl1);
                    mma_bf16_16816(C[fm][fn], al[fm][0], al[fm][1], al[fm][2], al[fm][3], bh0, bh1);
                }
            }
        }
    }

    __nv_bfloat16 zero = __float2bfloat16(0.0f);
    #pragma unroll
    for (int fm = 0; fm < 2; ++fm) {
        int obase = o0 + wm * 32 + fm * 16 + g;
        float bias0 = g_Bf[obase], bias1 = g_Bf[obase + 8];
        #pragma unroll
        for (int fn = 0; fn < 8; ++fn) {
            int bncol = bn0 + wn * 64 + fn * 8 + 2 * t;
            int b = bncol >> 12, n = bncol & 4095;
            #pragma unroll
            for (int rr = 0; rr < 2; ++rr) {
                int o = obase + rr * 8;
                float v0 = fmaxf(C[fm][fn][rr * 2 + 0] + (rr ? bias1 : bias0), 0.0f);
                float v1 = fmaxf(C[fm][fn][rr * 2 + 1] + (rr ? bias1 : bias0), 0.0f);
                if (o >= 64) {
                    *(uint32_t*)(g_Vb + ((size_t)b * CN + (o - 64)) * NN + n) = pack_bf2(v0, v1);
                } else {
                    #pragma unroll
                    for (int e = 0; e < 2; ++e) {
                        float v = e ? v1 : v0;
                        __nv_bfloat16 hi = __float2bfloat16(v);
                        __nv_bfloat16 lo = __float2bfloat16(v - __bfloat162float(hi));
                        size_t base = ((size_t)b * NN + n + e) * 128;
                        if (o < 32) {
                            g_Qb[base + o] = hi; g_Qb[base + 32 + o] = lo;
                            g_Qb[base + 64 + o] = hi; g_Qb[base + 96 + o] = zero;
                        } else {
                            int oc = o - 32;
                            g_Kb[base + oc] = hi; g_Kb[base + 32 + oc] = hi;
                            g_Kb[base + 64 + oc] = lo; g_Kb[base + 96 + oc] = zero;
                        }
                    }
                }
            }
        }
    }
}

// ---------------- flash attention: channel-major PV, NT=64, ldmatrix (non-trans) ----------------
#define KS_OFF 0
#define KS_BUF 13312
#define VS_OFF 26624
#define VS_BUF 36864
#define PS_OFF 100352
#define STM_OFF 109568
#define STL_OFF 110080
#define STF_OFF 110592
#define FLG_OFF 110848
#define INV_OFF 110864
#define SM_TOT 111616

__global__ void __launch_bounds__(256, 2)
flash_mma(const float* __restrict__ x, float* __restrict__ out) {
    extern __shared__ __align__(16) char smem[];
    uint32_t sb = smem_u32(smem);
    int tid = threadIdx.x;
    int lane = tid & 31, wid = tid >> 5;
    int g = lane >> 2, t = lane & 3;
    int mrow = wid & 3, khalf = wid >> 2;
    int q0 = mrow * 16;
    int ch0 = wid * 32;
    int b = blockIdx.y, m0 = blockIdx.x * 64;

    float* stM = (float*)(smem + STM_OFF);
    float* stL = (float*)(smem + STL_OFF);
    float* stF = (float*)(smem + STF_OFF);
    uint32_t* flg = (uint32_t*)(smem + FLG_OFF);
    float* inv = (float*)(smem + INV_OFF);

    // ldmatrix lane-address components (loop-invariant)
    int lm_r8  = (lane >> 4) << 3;       // +8 rows for matrices 2,3
    int lm_hi  = (lane >> 3) & 1;        // second-16B-column flag (matrices 1,3)
    int lm_row = lane & 7;
    // K B-frags: rows = keys (m0/m1 = keys 0-7 k-lo/k-hi, m2/m3 = keys 8-15)
    uint32_t kfrag_off = (uint32_t)((khalf * 32 + lm_r8 + lm_row) * 208 + lm_hi * 16);
    // V A-frags: m0 = rows 0-7 k-lo, m1 = rows 8-15 k-lo, m2 = rows 0-7 k-hi, m3 = rows 8-15 k-hi
    uint32_t vfrag_off = (uint32_t)((ch0 + lm_row + lm_hi * 8) * 144 + ((lane >> 4) << 4));
    // P B-frags: rows = q
    uint32_t pfrag_base = sb + PS_OFF + (uint32_t)((lm_r8 + lm_row) * 144 + lm_hi * 16);

    uint32_t qa[6][4];
    {
        const __nv_bfloat16* qr0 = g_Qb + ((size_t)b * NN + m0 + q0 + g) * 128;
        const __nv_bfloat16* qr1 = qr0 + (size_t)8 * 128;
        #pragma unroll
        for (int ks = 0; ks < 6; ++ks) {
            int e = ks * 16 + 2 * t;
            qa[ks][0] = *(const uint32_t*)(qr0 + e);
            qa[ks][1] = *(const uint32_t*)(qr1 + e);
            qa[ks][2] = *(const uint32_t*)(qr0 + e + 8);
            qa[ks][3] = *(const uint32_t*)(qr1 + e + 8);
        }
    }

    const char* kgb = (const char*)(g_Kb + ((size_t)b * NN) * 128);
    const char* vgb = (const char*)(g_Vb + (size_t)b * CN * NN);

    // prefetch chunk 0 into buf 0
    {
        #pragma unroll
        for (int i = tid; i < 768; i += 256) {
            int row = i / 12, col = i - row * 12;
            cp16(sb + KS_OFF + row * 208 + col * 16, kgb + (size_t)row * 256 + col * 16);
        }
        #pragma unroll
        for (int i = tid; i < 2048; i += 256) {
            int c = i >> 3, j = i & 7;
            cp16(sb + VS_OFF + c * 144 + j * 16, vgb + (size_t)c * (NN * 2) + j * 16);
        }
        CP_COMMIT();
    }

    float D[2][8][4];
    #pragma unroll
    for (int fm = 0; fm < 2; ++fm)
        #pragma unroll
        for (int fn = 0; fn < 8; ++fn) { D[fm][fn][0] = D[fm][fn][1] = D[fm][fn][2] = D[fm][fn][3] = 0.0f; }
    float m_run0 = -1e30f, m_run1 = -1e30f, l_run0 = 0.0f, l_run1 = 0.0f;

    for (int ch = 0; ch < 64; ++ch) {
        int buf = ch & 1;
        __syncthreads();   // B1
        if (ch + 1 < 64) {
            int n1 = (ch + 1) * 64;
            uint32_t kd = sb + KS_OFF + (buf ^ 1) * KS_BUF;
            uint32_t vd = sb + VS_OFF + (buf ^ 1) * VS_BUF;
            #pragma unroll
            for (int i = tid; i < 768; i += 256) {
                int row = i / 12, col = i - row * 12;
                cp16(kd + row * 208 + col * 16, kgb + (size_t)(n1 + row) * 256 + col * 16);
            }
            #pragma unroll
            for (int i = tid; i < 2048; i += 256) {
                int c = i >> 3, j = i & 7;
                cp16(vd + c * 144 + j * 16, vgb + (size_t)c * (NN * 2) + (size_t)n1 * 2 + j * 16);
            }
        }
        CP_COMMIT();
        CP_WAIT1();
        __syncthreads();   // B2

        // ---- score role: s[16q][32k] via ldmatrix (non-trans B frags) ----
        uint32_t ksmb = sb + KS_OFF + buf * KS_BUF + kfrag_off;
        float sc[4][4] = {};
        #pragma unroll
        for (int ks = 0; ks < 6; ++ks) {
            #pragma unroll
            for (int half = 0; half < 2; ++half) {
                uint32_t b00, b01, b10, b11;
                ldsm4(b00, b01, b10, b11, ksmb + half * (16 * 208) + ks * 32);
                mma_bf16_16816(sc[half * 2 + 0], qa[ks][0], qa[ks][1], qa[ks][2], qa[ks][3], b00, b01);
                mma_bf16_16816(sc[half * 2 + 1], qa[ks][0], qa[ks][1], qa[ks][2], qa[ks][3], b10, b11);
            }
        }
        float mp0 = fmaxf(fmaxf(sc[0][0], sc[0][1]), fmaxf(sc[1][0], sc[1][1]));
        mp0 = fmaxf(mp0, fmaxf(fmaxf(sc[2][0], sc[2][1]), fmaxf(sc[3][0], sc[3][1])));
        float mp1 = fmaxf(fmaxf(sc[0][2], sc[0][3]), fmaxf(sc[1][2], sc[1][3]));
        mp1 = fmaxf(mp1, fmaxf(fmaxf(sc[2][2], sc[2][3]), fmaxf(sc[3][2], sc[3][3])));
        mp0 = fmaxf(mp0, __shfl_xor_sync(0xffffffffu, mp0, 1));
        mp0 = fmaxf(mp0, __shfl_xor_sync(0xffffffffu, mp0, 2));
        mp1 = fmaxf(mp1, __shfl_xor_sync(0xffffffffu, mp1, 1));
        mp1 = fmaxf(mp1, __shfl_xor_sync(0xffffffffu, mp1, 2));
        if (t == 0) {
            stM[khalf * 64 + q0 + g] = mp0;
            stM[khalf * 64 + q0 + 8 + g] = mp1;
        }
        __syncthreads();   // B3
        float mt0 = fmaxf(stM[q0 + g], stM[64 + q0 + g]);
        float mt1 = fmaxf(stM[q0 + 8 + g], stM[64 + q0 + 8 + g]);
        float mn0 = fmaxf(m_run0, mt0), mn1 = fmaxf(m_run1, mt1);
        float f0 = __expf(m_run0 - mn0), f1 = __expf(m_run1 - mn1);
        m_run0 = mn0; m_run1 = mn1;

        float ls0 = 0.0f, ls1 = 0.0f;
        #pragma unroll
        for (int nt = 0; nt < 4; ++nt) {
            float e0 = __expf(sc[nt][0] - mn0);
            float e1 = __expf(sc[nt][1] - mn0);
            float e2 = __expf(sc[nt][2] - mn1);
            float e3 = __expf(sc[nt][3] - mn1);
            ls0 += e0 + e1; ls1 += e2 + e3;
            char* pr0 = smem + PS_OFF + (q0 + g) * 144 + khalf * 64 + nt * 16 + t * 4;
            char* pr1 = smem + PS_OFF + (q0 + 8 + g) * 144 + khalf * 64 + nt * 16 + t * 4;
            *(uint32_t*)(pr0) = pack_bf2(e0, e1);
            *(uint32_t*)(pr1) = pack_bf2(e2, e3);
        }
        uint32_t nb = __ballot_sync(0xffffffffu, (f0 < 1.0f) || (f1 < 1.0f));
        if (khalf == 0 && t == 0) {
            stF[q0 + g] = f0;
            stF[q0 + 8 + g] = f1;
        }
        if (khalf == 0 && lane == 0) flg[mrow] = nb;
        ls0 += __shfl_xor_sync(0xffffffffu, ls0, 1);
        ls0 += __shfl_xor_sync(0xffffffffu, ls0, 2);
        ls1 += __shfl_xor_sync(0xffffffffu, ls1, 1);
        ls1 += __shfl_xor_sync(0xffffffffu, ls1, 2);
        if (t == 0) {
            stL[khalf * 64 + q0 + g] = ls0;
            stL[khalf * 64 + q0 + 8 + g] = ls1;
        }
        __syncthreads();   // B4
        l_run0 = l_run0 * f0 + stL[q0 + g] + stL[64 + q0 + g];
        l_run1 = l_run1 * f1 + stL[q0 + 8 + g] + stL[64 + q0 + 8 + g];

        // ---- PV role: D[32ch][64q] += V[32ch][64k] * P[64k][64q] via ldmatrix ----
        if (flg[0] | flg[1] | flg[2] | flg[3]) {
            #pragma unroll
            for (int fn = 0; fn < 8; ++fn) {
                float2 ff = *(float2*)(stF + fn * 8 + 2 * t);
                #pragma unroll
                for (int fm = 0; fm < 2; ++fm) {
                    D[fm][fn][0] *= ff.x; D[fm][fn][1] *= ff.y;
                    D[fm][fn][2] *= ff.x; D[fm][fn][3] *= ff.y;
                }
            }
        }
        uint32_t vsmb = sb + VS_OFF + buf * VS_BUF + vfrag_off;
        #pragma unroll
        for (int ks = 0; ks < 4; ++ks) {
            uint32_t va[2][4];
            ldsm4(va[0][0], va[0][1], va[0][2], va[0][3], vsmb + ks * 32);
            ldsm4(va[1][0], va[1][1], va[1][2], va[1][3], vsmb + 16 * 144 + ks * 32);
            #pragma unroll
            for (int fnp = 0; fnp < 4; ++fnp) {
                uint32_t p00, p01, p10, p11;
                ldsm4(p00, p01, p10, p11, pfrag_base + fnp * (16 * 144) + ks * 32);
                mma_bf16_16816(D[0][fnp * 2 + 0], va[0][0], va[0][1], va[0][2], va[0][3], p00, p01);
                mma_bf16_16816(D[1][fnp * 2 + 0], va[1][0], va[1][1], va[1][2], va[1][3], p00, p01);
                mma_bf16_16816(D[0][fnp * 2 + 1], va[0][0], va[0][1], va[0][2], va[0][3], p10, p11);
                mma_bf16_16816(D[1][fnp * 2 + 1], va[1][0], va[1][1], va[1][2], va[1][3], p10, p11);
            }
        }
    }

    // publish final 1/l per query
    if (khalf == 0 && t == 0) {
        inv[q0 + g] = 1.0f / l_run0;
        inv[q0 + 8 + g] = 1.0f / l_run1;
    }
    __syncthreads();

    // ---- epilogue: out[ch][m0+q] = x + D * inv[q], direct coalesced ----
    const float* xb = x + (size_t)b * CN * NN + m0;
    float* ob = out + (size_t)b * CN * NN + m0;
    #pragma unroll
    for (int fn = 0; fn < 8; ++fn) {
        int q = fn * 8 + 2 * t;
        float2 iv = *(float2*)(inv + q);
        #pragma unroll
        for (int fm = 0; fm < 2; ++fm) {
            int chv = ch0 + fm * 16 + g;
            size_t o1 = (size_t)chv * NN + q;
            float2 x1 = *(const float2*)(xb + o1);
            float2 w1;
            w1.x = x1.x + D[fm][fn][0] * iv.x;
            w1.y = x1.y + D[fm][fn][1] * iv.y;
            *(float2*)(ob + o1) = w1;
            size_t o2 = (size_t)(chv + 8) * NN + q;
            float2 x2 = *(const float2*)(xb + o2);
            float2 w2;
            w2.x = x2.x + D[fm][fn][2] * iv.x;
            w2.y = x2.y + D[fm][fn][3] * iv.y;
            *(float2*)(ob + o2) = w2;
        }
    }
}

// ---------------- launcher ----------------
extern "C" void kernel_launch(void* const* d_in, const int* in_sizes, int n_in,
                              void* d_out, int out_size) {
    const float* x  = (const float*)d_in[0];
    const float* w1 = (const float*)d_in[1];
    const float* w2 = (const float*)d_in[2];
    const float* w3 = (const float*)d_in[3];
    const float* g1 = (const float*)d_in[4];
    const float* b1 = (const float*)d_in[5];
    const float* g2 = (const float*)d_in[6];
    const float* b2 = (const float*)d_in[7];
    const float* g3 = (const float*)d_in[8];
    const float* b3 = (const float*)d_in[9];
    float* out = (float*)d_out;

    cudaFuncSetAttribute(flash_mma, cudaFuncAttributeMaxDynamicSharedMemorySize, SM_TOT);
    cudaFuncSetAttribute(qkd_mma, cudaFuncAttributeMaxDynamicSharedMemorySize, QK_SM);

    zero_kernel<<<256, 256>>>();
    convx_kernel<<<dim3(64, 4, 4), 256>>>(x);
    gram_mma<<<dim3(10, 1, 16), 256>>>(0);
    fold_kernel<<<320, 256>>>(w1, w2, w3, g1, b1, g2, b2, g3, b3);
    qkd_mma<<<dim3(5, 64), 256, QK_SM>>>(0);
    flash_mma<<<dim3(64, 4), 256, SM_TOT>>>(x, out);
}

// round 15
// speedup vs baseline: 1.1868x; 1.0269x over previous
#include <cuda_runtime.h>
#include <cuda_bf16.h>
#include <cstdint>

#define BB 4
#define CN 256
#define NN 4096
#define OTOT 320
#define BN_TOT 16384.0f
#define KTOT 16384

// ---------------- device scratch ----------------
__device__ float g_mx[CN];                            // raw channel sums
__device__ float g_G[CN * CN];
__device__ float g_Bf[OTOT];
__device__ __nv_bfloat16 g_Wh[OTOT * CN];             // folded W hi, [o][c]
__device__ __nv_bfloat16 g_Wl[OTOT * CN];             // folded W lo, [o][c]
__device__ __nv_bfloat16 g_xh[(size_t)CN * KTOT];     // x hi, [c][b*n]
__device__ __nv_bfloat16 g_xl[(size_t)CN * KTOT];     // x lo, [c][b*n]
__device__ __nv_bfloat16 g_xTh[(size_t)KTOT * CN];    // x hi, [b*n][c]
__device__ __nv_bfloat16 g_xTl[(size_t)KTOT * CN];    // x lo, [b*n][c]
__device__ __nv_bfloat16 g_Qb[(size_t)BB * NN * 128]; // [b][n][qhi32|qlo32|qhi32|0]
__device__ __nv_bfloat16 g_Kb[(size_t)BB * NN * 128]; // [b][n][khi32|khi32|klo32|0]
__device__ __nv_bfloat16 g_Vb[(size_t)BB * CN * NN];  // bf16, [b][c][n]

// ---------------- mma.sync / async helpers ----------------
__device__ __forceinline__ void mma_bf16_16816(float* c, uint32_t a0, uint32_t a1,
                                               uint32_t a2, uint32_t a3,
                                               uint32_t b0, uint32_t b1) {
    asm volatile("mma.sync.aligned.m16n8k16.row.col.f32.bf16.bf16.f32 "
        "{%0,%1,%2,%3}, {%4,%5,%6,%7}, {%8,%9}, {%0,%1,%2,%3};"
        : "+f"(c[0]), "+f"(c[1]), "+f"(c[2]), "+f"(c[3])
        : "r"(a0), "r"(a1), "r"(a2), "r"(a3), "r"(b0), "r"(b1));
}
__device__ __forceinline__ void ldsm4(uint32_t& r0, uint32_t& r1, uint32_t& r2, uint32_t& r3,
                                      uint32_t a) {
    asm volatile("ldmatrix.sync.aligned.m8n8.x4.shared.b16 {%0,%1,%2,%3}, [%4];"
        : "=r"(r0), "=r"(r1), "=r"(r2), "=r"(r3) : "r"(a));
}
__device__ __forceinline__ void cp16(uint32_t dst, const void* src) {
    asm volatile("cp.async.cg.shared.global [%0], [%1], 16;" :: "r"(dst), "l"(src));
}
#define CP_COMMIT() asm volatile("cp.async.commit_group;" ::: "memory")
#define CP_WAIT0()  asm volatile("cp.async.wait_group 0;" ::: "memory")
#define CP_WAIT1()  asm volatile("cp.async.wait_group 1;" ::: "memory")
__device__ __forceinline__ uint32_t smem_u32(const void* p) {
    uint32_t a;
    asm("{ .reg .u64 t; cvta.to.shared.u64 t, %1; cvt.u32.u64 %0, t; }" : "=r"(a) : "l"(p));
    return a;
}
__device__ __forceinline__ uint32_t pack_bf2(float a, float b) {
    __nv_bfloat162 h = __floats2bfloat162_rn(a, b);
    return *(uint32_t*)&h;
}

// ---------------- prologue ----------------
__global__ void zero_kernel() {
    int i = blockIdx.x * blockDim.x + threadIdx.x;
    g_G[i] = 0.0f;
    if (i < CN) g_mx[i] = 0.0f;
}

// tiled transpose/convert: x -> bf16 hi/lo in [c][bn] AND [bn][c]; fused channel sums
__global__ void convx_kernel(const float* __restrict__ x) {
    __shared__ float tile[64][65];
    int n0 = blockIdx.x * 64, c0 = blockIdx.y * 64, b = blockIdx.z;
    int tid = threadIdx.x;
    int rr = tid >> 6, jj = tid & 63;
    const float* xb = x + ((size_t)b * CN + c0) * NN + n0;
    #pragma unroll
    for (int r = 0; r < 16; ++r) {
        int i = r * 4 + rr;
        tile[i][jj] = xb[(size_t)i * NN + jj];
    }
    __syncthreads();
    if (tid < 64) {
        float s = 0.0f;
        #pragma unroll
        for (int j = 0; j < 64; ++j) s += tile[tid][j];
        atomicAdd(&g_mx[c0 + tid], s);
    }
    size_t bn0 = (size_t)b * NN + n0;
    #pragma unroll
    for (int r = 0; r < 16; ++r) {
        int i = r * 4 + rr;
        float v = tile[i][jj];
        __nv_bfloat16 hi = __float2bfloat16(v);
        __nv_bfloat16 lo = __float2bfloat16(v - __bfloat162float(hi));
        size_t off = (size_t)(c0 + i) * KTOT + bn0 + jj;
        g_xh[off] = hi; g_xl[off] = lo;
    }
    #pragma unroll
    for (int r = 0; r < 16; ++r) {
        int i = r * 4 + rr;           // n index
        float v = tile[jj][i];        // [c=jj][n=i]
        __nv_bfloat16 hi = __float2bfloat16(v);
        __nv_bfloat16 lo = __float2bfloat16(v - __bfloat162float(hi));
        size_t off = (bn0 + i) * CN + c0 + jj;
        g_xTh[off] = hi; g_xTl[off] = lo;
    }
}

// ---------------- Gram via mma.sync (hi/lo, symmetric, ldmatrix frags) ----------------
#define GR_STRIDE 144
#define GR_MAT (64 * GR_STRIDE)
__global__ void __launch_bounds__(256, 2)
gram_mma(int dummy) {
    __shared__ __align__(16) char smem[4 * GR_MAT];
    uint32_t sb = smem_u32(smem);
    int tid = threadIdx.x;
    int lane = tid & 31, wid = tid >> 5;
    int g = lane >> 2, t = lane & 3;
    int wm = wid >> 2, wn = wid & 3;
    int lm_r8  = (lane >> 4) << 3;
    int lm_hi  = (lane >> 3) & 1;
    int lm_row = lane & 7;
    int r4 = 0, rem = blockIdx.x;
    while (rem >= 4 - r4) { rem -= 4 - r4; ++r4; }
    int c4 = r4 + rem;
    int c0 = r4 * 64, c1 = c4 * 64;
    int kseg = blockIdx.z * 1024;

    // A frags (rows wm*32 + fm*16): flash-V style mapping
    uint32_t aoffA = (uint32_t)((wm * 32 + lm_row + lm_hi * 8) * GR_STRIDE + ((lane >> 4) << 4));
    // B frags (rows wn*16, covers fn 0/1): flash-K style mapping
    uint32_t aoffB = (uint32_t)((wn * 16 + lm_r8 + lm_row) * GR_STRIDE + lm_hi * 16);

    float C[2][2][4] = {};

    for (int ch = 0; ch < 16; ++ch) {
        int k0 = kseg + ch * 64;
        __syncthreads();
        #pragma unroll
        for (int i = tid; i < 512; i += 256) {
            int row = i >> 3, col = i & 7;
            cp16(sb + 0 * GR_MAT + row * GR_STRIDE + col * 16,
                 g_xh + (size_t)(c0 + row) * KTOT + k0 + col * 8);
            cp16(sb + 1 * GR_MAT + row * GR_STRIDE + col * 16,
                 g_xl + (size_t)(c0 + row) * KTOT + k0 + col * 8);
            cp16(sb + 2 * GR_MAT + row * GR_STRIDE + col * 16,
                 g_xh + (size_t)(c1 + row) * KTOT + k0 + col * 8);
            cp16(sb + 3 * GR_MAT + row * GR_STRIDE + col * 16,
                 g_xl + (size_t)(c1 + row) * KTOT + k0 + col * 8);
        }
        CP_COMMIT();
        CP_WAIT0();
        __syncthreads();
        #pragma unroll
        for (int ks = 0; ks < 4; ++ks) {
            uint32_t ah[2][4], al[2][4], bh[4], bl[4];
            ldsm4(ah[0][0], ah[0][1], ah[0][2], ah[0][3], sb + 0 * GR_MAT + aoffA + ks * 32);
            ldsm4(ah[1][0], ah[1][1], ah[1][2], ah[1][3], sb + 0 * GR_MAT + aoffA + 16 * GR_STRIDE + ks * 32);
            ldsm4(al[0][0], al[0][1], al[0][2], al[0][3], sb + 1 * GR_MAT + aoffA + ks * 32);
            ldsm4(al[1][0], al[1][1], al[1][2], al[1][3], sb + 1 * GR_MAT + aoffA + 16 * GR_STRIDE + ks * 32);
            ldsm4(bh[0], bh[1], bh[2], bh[3], sb + 2 * GR_MAT + aoffB + ks * 32);
            ldsm4(bl[0], bl[1], bl[2], bl[3], sb + 3 * GR_MAT + aoffB + ks * 32);
            #pragma unroll
            for (int fn = 0; fn < 2; ++fn) {
                #pragma unroll
                for (int fm = 0; fm < 2; ++fm) {
                    mma_bf16_16816(C[fm][fn], ah[fm][0], ah[fm][1], ah[fm][2], ah[fm][3], bh[2*fn], bh[2*fn+1]);
                    mma_bf16_16816(C[fm][fn], ah[fm][0], ah[fm][1], ah[fm][2], ah[fm][3], bl[2*fn], bl[2*fn+1]);
                    mma_bf16_16816(C[fm][fn], al[fm][0], al[fm][1], al[fm][2], al[fm][3], bh[2*fn], bh[2*fn+1]);
                }
            }
        }
    }
    int mirror = (c0 != c1);
    #pragma unroll
    for (int fm = 0; fm < 2; ++fm) {
        #pragma unroll
        for (int fn = 0; fn < 2; ++fn) {
            int r0 = c0 + wm * 32 + fm * 16 + g;
            int cc = c1 + wn * 16 + fn * 8 + 2 * t;
            atomicAdd(&g_G[r0 * CN + cc],           C[fm][fn][0]);
            atomicAdd(&g_G[r0 * CN + cc + 1],       C[fm][fn][1]);
            atomicAdd(&g_G[(r0 + 8) * CN + cc],     C[fm][fn][2]);
            atomicAdd(&g_G[(r0 + 8) * CN + cc + 1], C[fm][fn][3]);
            if (mirror) {
                atomicAdd(&g_G[cc * CN + r0],           C[fm][fn][0]);
                atomicAdd(&g_G[(cc + 1) * CN + r0],     C[fm][fn][1]);
                atomicAdd(&g_G[cc * CN + r0 + 8],       C[fm][fn][2]);
                atomicAdd(&g_G[(cc + 1) * CN + r0 + 8], C[fm][fn][3]);
            }
        }
    }
}

// ---------------- fold BN (320 blocks, ILP accumulators) ----------------
__global__ void fold_kernel(const float* __restrict__ w1, const float* __restrict__ w2,
                            const float* __restrict__ w3,
                            const float* __restrict__ g1, const float* __restrict__ b1,
                            const float* __restrict__ g2, const float* __restrict__ b2,
                            const float* __restrict__ g3, const float* __restrict__ b3) {
    int o = blockIdx.x, tid = threadIdx.x;
    const float* w; float gg, bb;
    if (o < 32)      { w = w1 + o * CN;        gg = g1[o];      bb = b1[o]; }
    else if (o < 64) { w = w2 + (o - 32) * CN; gg = g2[o - 32]; bb = b2[o - 32]; }
    else             { w = w3 + (o - 64) * CN; gg = g3[o - 64]; bb = b3[o - 64]; }
    __shared__ float ws[256], redE[256], redM[256], sc_sh;
    ws[tid] = w[tid]; __syncthreads();
    float a0 = 0.0f, a1 = 0.0f, a2 = 0.0f, a3 = 0.0f;
    #pragma unroll 8
    for (int c = 0; c < CN; c += 4) {
        a0 += g_G[(c + 0) * CN + tid] * ws[c + 0];
        a1 += g_G[(c + 1) * CN + tid] * ws[c + 1];
        a2 += g_G[(c + 2) * CN + tid] * ws[c + 2];
        a3 += g_G[(c + 3) * CN + tid] * ws[c + 3];
    }
    redE[tid] = (a0 + a1 + a2 + a3) * ws[tid];
    redM[tid] = ws[tid] * g_mx[tid] * (1.0f / BN_TOT);
    __syncthreads();
    for (int st = 128; st > 0; st >>= 1) {
        if (tid < st) { redE[tid] += redE[tid + st]; redM[tid] += redM[tid + st]; }
        __syncthreads();
    }
    if (tid == 0) {
        float m = redM[0], E = redE[0] * (1.0f / BN_TOT);
        float rs = rsqrtf(E - m * m + 1e-5f);
        float sc = gg * rs;
        sc_sh = sc;
        g_Bf[o] = bb - sc * m;
    }
    __syncthreads();
    float wf = sc_sh * ws[tid];
    __nv_bfloat16 hi = __float2bfloat16(wf);
    __nv_bfloat16 lo = __float2bfloat16(wf - __bfloat162float(hi));
    g_Wh[o * CN + tid] = hi;
    g_Wl[o * CN + tid] = lo;
}

// ---------------- qkd via mma.sync + ldmatrix: Z[o][bn] = relu(W x + b) ----------------
#define QK_SM 92160
__global__ void __launch_bounds__(256, 2)
qkd_mma(int dummy) {
    extern __shared__ __align__(16) char smem[];
    uint32_t sb = smem_u32(smem);
    int tid = threadIdx.x;
    int lane = tid & 31, wid = tid >> 5;
    int g = lane >> 2, t = lane & 3;
    int wm = wid >> 2, wn = wid & 3;
    int lm_r8  = (lane >> 4) << 3;
    int lm_hi  = (lane >> 3) & 1;
    int lm_row = lane & 7;
    int o0 = blockIdx.x * 64;
    int bn0 = blockIdx.y * 256;

    // A frags (W rows wm*32 + fm*16)
    uint32_t aoffW = (uint32_t)((wm * 32 + lm_row + lm_hi * 8) * 144 + ((lane >> 4) << 4));
    // B frags (X rows wn*64 + fng*16)
    uint32_t aoffX = (uint32_t)((wn * 64 + lm_r8 + lm_row) * 144 + lm_hi * 16);

    float C[2][8][4] = {};

    for (int kc = 0; kc < 4; ++kc) {
        int k0 = kc * 64;
        __syncthreads();
        #pragma unroll
        for (int i = tid; i < 512; i += 256) {
            int row = i >> 3, col = i & 7;
            cp16(sb + row * 144 + col * 16,        g_Wh + (size_t)(o0 + row) * CN + k0 + col * 8);
            cp16(sb + 9216 + row * 144 + col * 16, g_Wl + (size_t)(o0 + row) * CN + k0 + col * 8);
        }
        #pragma unroll
        for (int i = tid; i < 2048; i += 256) {
            int row = i >> 3, col = i & 7;
            cp16(sb + 18432 + row * 144 + col * 16, g_xTh + (bn0 + row) * (size_t)CN + k0 + col * 8);
            cp16(sb + 55296 + row * 144 + col * 16, g_xTl + (bn0 + row) * (size_t)CN + k0 + col * 8);
        }
        CP_COMMIT();
        CP_WAIT0();
        __syncthreads();
        #pragma unroll
        for (int ks = 0; ks < 4; ++ks) {
            uint32_t ah[2][4], al[2][4];
            ldsm4(ah[0][0], ah[0][1], ah[0][2], ah[0][3], sb + aoffW + ks * 32);
            ldsm4(ah[1][0], ah[1][1], ah[1][2], ah[1][3], sb + aoffW + 16 * 144 + ks * 32);
            ldsm4(al[0][0], al[0][1], al[0][2], al[0][3], sb + 9216 + aoffW + ks * 32);
            ldsm4(al[1][0], al[1][1], al[1][2], al[1][3], sb + 9216 + aoffW + 16 * 144 + ks * 32);
            #pragma unroll
            for (int fng = 0; fng < 4; ++fng) {
                uint32_t bh[4], bl[4];
                ldsm4(bh[0], bh[1], bh[2], bh[3], sb + 18432 + aoffX + fng * (16 * 144) + ks * 32);
                ldsm4(bl[0], bl[1], bl[2], bl[3], sb + 55296 + aoffX + fng * (16 * 144) + ks * 32);
                #pragma unroll
                for (int half = 0; half < 2; ++half) {
                    int fn = fng * 2 + half;
                    #pragma unroll
                    for (int fm = 0; fm < 2; ++fm) {
                        mma_bf16_16816(C[fm][fn], ah[fm][0], ah[fm][1], ah[fm][2], ah[fm][3], bh[2*half], bh[2*half+1]);
                        mma_bf16_16816(C[fm][fn], ah[fm][0], ah[fm][1], ah[fm][2], ah[fm][3], bl[2*half], bl[2*half+1]);
                        mma_bf16_16816(C[fm][fn], al[fm][0], al[fm][1], al[fm][2], al[fm][3], bh[2*half], bh[2*half+1]);
                    }
                }
            }
        }
    }

    __nv_bfloat16 zero = __float2bfloat16(0.0f);
    #pragma unroll
    for (int fm = 0; fm < 2; ++fm) {
        int obase = o0 + wm * 32 + fm * 16 + g;
        float bias0 = g_Bf[obase], bias1 = g_Bf[obase + 8];
        #pragma unroll
        for (int fn = 0; fn < 8; ++fn) {
            int bncol = bn0 + wn * 64 + fn * 8 + 2 * t;
            int b = bncol >> 12, n = bncol & 4095;
            #pragma unroll
            for (int rr = 0; rr < 2; ++rr) {
                int o = obase + rr * 8;
                float v0 = fmaxf(C[fm][fn][rr * 2 + 0] + (rr ? bias1 : bias0), 0.0f);
                float v1 = fmaxf(C[fm][fn][rr * 2 + 1] + (rr ? bias1 : bias0), 0.0f);
                if (o >= 64) {
                    *(uint32_t*)(g_Vb + ((size_t)b * CN + (o - 64)) * NN + n) = pack_bf2(v0, v1);
                } else {
                    #pragma unroll
                    for (int e = 0; e < 2; ++e) {
                        float v = e ? v1 : v0;
                        __nv_bfloat16 hi = __float2bfloat16(v);
                        __nv_bfloat16 lo = __float2bfloat16(v - __bfloat162float(hi));
                        size_t base = ((size_t)b * NN + n + e) * 128;
                        if (o < 32) {
                            g_Qb[base + o] = hi; g_Qb[base + 32 + o] = lo;
                            g_Qb[base + 64 + o] = hi; g_Qb[base + 96 + o] = zero;
                        } else {
                            int oc = o - 32;
                            g_Kb[base + oc] = hi; g_Kb[base + 32 + oc] = hi;
                            g_Kb[base + 64 + oc] = lo; g_Kb[base + 96 + oc] = zero;
                        }
                    }
                }
            }
        }
    }
}

// ---------------- flash attention: channel-major PV, NT=64, ldmatrix (round-14, frozen) ----------------
#define KS_OFF 0
#define KS_BUF 13312
#define VS_OFF 26624
#define VS_BUF 36864
#define PS_OFF 100352
#define STM_OFF 109568
#define STL_OFF 110080
#define STF_OFF 110592
#define FLG_OFF 110848
#define INV_OFF 110864
#define SM_TOT 111616

__global__ void __launch_bounds__(256, 2)
flash_mma(const float* __restrict__ x, float* __restrict__ out) {
    extern __shared__ __align__(16) char smem[];
    uint32_t sb = smem_u32(smem);
    int tid = threadIdx.x;
    int lane = tid & 31, wid = tid >> 5;
    int g = lane >> 2, t = lane & 3;
    int mrow = wid & 3, khalf = wid >> 2;
    int q0 = mrow * 16;
    int ch0 = wid * 32;
    int b = blockIdx.y, m0 = blockIdx.x * 64;

    float* stM = (float*)(smem + STM_OFF);
    float* stL = (float*)(smem + STL_OFF);
    float* stF = (float*)(smem + STF_OFF);
    uint32_t* flg = (uint32_t*)(smem + FLG_OFF);
    float* inv = (float*)(smem + INV_OFF);

    int lm_r8  = (lane >> 4) << 3;
    int lm_hi  = (lane >> 3) & 1;
    int lm_row = lane & 7;
    uint32_t kfrag_off = (uint32_t)((khalf * 32 + lm_r8 + lm_row) * 208 + lm_hi * 16);
    uint32_t vfrag_off = (uint32_t)((ch0 + lm_row + lm_hi * 8) * 144 + ((lane >> 4) << 4));
    uint32_t pfrag_base = sb + PS_OFF + (uint32_t)((lm_r8 + lm_row) * 144 + lm_hi * 16);

    uint32_t qa[6][4];
    {
        const __nv_bfloat16* qr0 = g_Qb + ((size_t)b * NN + m0 + q0 + g) * 128;
        const __nv_bfloat16* qr1 = qr0 + (size_t)8 * 128;
        #pragma unroll
        for (int ks = 0; ks < 6; ++ks) {
            int e = ks * 16 + 2 * t;
            qa[ks][0] = *(const uint32_t*)(qr0 + e);
            qa[ks][1] = *(const uint32_t*)(qr1 + e);
            qa[ks][2] = *(const uint32_t*)(qr0 + e + 8);
            qa[ks][3] = *(const uint32_t*)(qr1 + e + 8);
        }
    }

    const char* kgb = (const char*)(g_Kb + ((size_t)b * NN) * 128);
    const char* vgb = (const char*)(g_Vb + (size_t)b * CN * NN);

    {
        #pragma unroll
        for (int i = tid; i < 768; i += 256) {
            int row = i / 12, col = i - row * 12;
            cp16(sb + KS_OFF + row * 208 + col * 16, kgb + (size_t)row * 256 + col * 16);
        }
        #pragma unroll
        for (int i = tid; i < 2048; i += 256) {
            int c = i >> 3, j = i & 7;
            cp16(sb + VS_OFF + c * 144 + j * 16, vgb + (size_t)c * (NN * 2) + j * 16);
        }
        CP_COMMIT();
    }

    float D[2][8][4];
    #pragma unroll
    for (int fm = 0; fm < 2; ++fm)
        #pragma unroll
        for (int fn = 0; fn < 8; ++fn) { D[fm][fn][0] = D[fm][fn][1] = D[fm][fn][2] = D[fm][fn][3] = 0.0f; }
    float m_run0 = -1e30f, m_run1 = -1e30f, l_run0 = 0.0f, l_run1 = 0.0f;

    for (int ch = 0; ch < 64; ++ch) {
        int buf = ch & 1;
        __syncthreads();   // B1
        if (ch + 1 < 64) {
            int n1 = (ch + 1) * 64;
            uint32_t kd = sb + KS_OFF + (buf ^ 1) * KS_BUF;
            uint32_t vd = sb + VS_OFF + (buf ^ 1) * VS_BUF;
            #pragma unroll
            for (int i = tid; i < 768; i += 256) {
                int row = i / 12, col = i - row * 12;
                cp16(kd + row * 208 + col * 16, kgb + (size_t)(n1 + row) * 256 + col * 16);
            }
            #pragma unroll
            for (int i = tid; i < 2048; i += 256) {
                int c = i >> 3, j = i & 7;
                cp16(vd + c * 144 + j * 16, vgb + (size_t)c * (NN * 2) + (size_t)n1 * 2 + j * 16);
            }
        }
        CP_COMMIT();
        CP_WAIT1();
        __syncthreads();   // B2

        uint32_t ksmb = sb + KS_OFF + buf * KS_BUF + kfrag_off;
        float sc[4][4] = {};
        #pragma unroll
        for (int ks = 0; ks < 6; ++ks) {
            #pragma unroll
            for (int half = 0; half < 2; ++half) {
                uint32_t b00, b01, b10, b11;
                ldsm4(b00, b01, b10, b11, ksmb + half * (16 * 208) + ks * 32);
                mma_bf16_16816(sc[half * 2 + 0], qa[ks][0], qa[ks][1], qa[ks][2], qa[ks][3], b00, b01);
                mma_bf16_16816(sc[half * 2 + 1], qa[ks][0], qa[ks][1], qa[ks][2], qa[ks][3], b10, b11);
            }
        }
        float mp0 = fmaxf(fmaxf(sc[0][0], sc[0][1]), fmaxf(sc[1][0], sc[1][1]));
        mp0 = fmaxf(mp0, fmaxf(fmaxf(sc[2][0], sc[2][1]), fmaxf(sc[3][0], sc[3][1])));
        float mp1 = fmaxf(fmaxf(sc[0][2], sc[0][3]), fmaxf(sc[1][2], sc[1][3]));
        mp1 = fmaxf(mp1, fmaxf(fmaxf(sc[2][2], sc[2][3]), fmaxf(sc[3][2], sc[3][3])));
        mp0 = fmaxf(mp0, __shfl_xor_sync(0xffffffffu, mp0, 1));
        mp0 = fmaxf(mp0, __shfl_xor_sync(0xffffffffu, mp0, 2));
        mp1 = fmaxf(mp1, __shfl_xor_sync(0xffffffffu, mp1, 1));
        mp1 = fmaxf(mp1, __shfl_xor_sync(0xffffffffu, mp1, 2));
        if (t == 0) {
            stM[khalf * 64 + q0 + g] = mp0;
            stM[khalf * 64 + q0 + 8 + g] = mp1;
        }
        __syncthreads();   // B3
        float mt0 = fmaxf(stM[q0 + g], stM[64 + q0 + g]);
        float mt1 = fmaxf(stM[q0 + 8 + g], stM[64 + q0 + 8 + g]);
        float mn0 = fmaxf(m_run0, mt0), mn1 = fmaxf(m_run1, mt1);
        float f0 = __expf(m_run0 - mn0), f1 = __expf(m_run1 - mn1);
        m_run0 = mn0; m_run1 = mn1;

        float ls0 = 0.0f, ls1 = 0.0f;
        #pragma unroll
        for (int nt = 0; nt < 4; ++nt) {
            float e0 = __expf(sc[nt][0] - mn0);
            float e1 = __expf(sc[nt][1] - mn0);
            float e2 = __expf(sc[nt][2] - mn1);
            float e3 = __expf(sc[nt][3] - mn1);
            ls0 += e0 + e1; ls1 += e2 + e3;
            char* pr0 = smem + PS_OFF + (q0 + g) * 144 + khalf * 64 + nt * 16 + t * 4;
            char* pr1 = smem + PS_OFF + (q0 + 8 + g) * 144 + khalf * 64 + nt * 16 + t * 4;
            *(uint32_t*)(pr0) = pack_bf2(e0, e1);
            *(uint32_t*)(pr1) = pack_bf2(e2, e3);
        }
        uint32_t nb = __ballot_sync(0xffffffffu, (f0 < 1.0f) || (f1 < 1.0f));
        if (khalf == 0 && t == 0) {
            stF[q0 + g] = f0;
            stF[q0 + 8 + g] = f1;
        }
        if (khalf == 0 && lane == 0) flg[mrow] = nb;
        ls0 += __shfl_xor_sync(0xffffffffu, ls0, 1);
        ls0 += __shfl_xor_sync(0xffffffffu, ls0, 2);
        ls1 += __shfl_xor_sync(0xffffffffu, ls1, 1);
        ls1 += __shfl_xor_sync(0xffffffffu, ls1, 2);
        if (t == 0) {
            stL[khalf * 64 + q0 + g] = ls0;
            stL[khalf * 64 + q0 + 8 + g] = ls1;
        }
        __syncthreads();   // B4
        l_run0 = l_run0 * f0 + stL[q0 + g] + stL[64 + q0 + g];
        l_run1 = l_run1 * f1 + stL[q0 + 8 + g] + stL[64 + q0 + 8 + g];

        if (flg[0] | flg[1] | flg[2] | flg[3]) {
            #pragma unroll
            for (int fn = 0; fn < 8; ++fn) {
                float2 ff = *(float2*)(stF + fn * 8 + 2 * t);
                #pragma unroll
                for (int fm = 0; fm < 2; ++fm) {
                    D[fm][fn][0] *= ff.x; D[fm][fn][1] *= ff.y;
                    D[fm][fn][2] *= ff.x; D[fm][fn][3] *= ff.y;
                }
            }
        }
        uint32_t vsmb = sb + VS_OFF + buf * VS_BUF + vfrag_off;
        #pragma unroll
        for (int ks = 0; ks < 4; ++ks) {
            uint32_t va[2][4];
            ldsm4(va[0][0], va[0][1], va[0][2], va[0][3], vsmb + ks * 32);
            ldsm4(va[1][0], va[1][1], va[1][2], va[1][3], vsmb + 16 * 144 + ks * 32);
            #pragma unroll
            for (int fnp = 0; fnp < 4; ++fnp) {
                uint32_t p00, p01, p10, p11;
                ldsm4(p00, p01, p10, p11, pfrag_base + fnp * (16 * 144) + ks * 32);
                mma_bf16_16816(D[0][fnp * 2 + 0], va[0][0], va[0][1], va[0][2], va[0][3], p00, p01);
                mma_bf16_16816(D[1][fnp * 2 + 0], va[1][0], va[1][1], va[1][2], va[1][3], p00, p01);
                mma_bf16_16816(D[0][fnp * 2 + 1], va[0][0], va[0][1], va[0][2], va[0][3], p10, p11);
                mma_bf16_16816(D[1][fnp * 2 + 1], va[1][0], va[1][1], va[1][2], va[1][3], p10, p11);
            }
        }
    }

    if (khalf == 0 && t == 0) {
        inv[q0 + g] = 1.0f / l_run0;
        inv[q0 + 8 + g] = 1.0f / l_run1;
    }
    __syncthreads();

    const float* xb = x + (size_t)b * CN * NN + m0;
    float* ob = out + (size_t)b * CN * NN + m0;
    #pragma unroll
    for (int fn = 0; fn < 8; ++fn) {
        int q = fn * 8 + 2 * t;
        float2 iv = *(float2*)(inv + q);
        #pragma unroll
        for (int fm = 0; fm < 2; ++fm) {
            int chv = ch0 + fm * 16 + g;
            size_t o1 = (size_t)chv * NN + q;
            float2 x1 = *(const float2*)(xb + o1);
            float2 w1;
            w1.x = x1.x + D[fm][fn][0] * iv.x;
            w1.y = x1.y + D[fm][fn][1] * iv.y;
            *(float2*)(ob + o1) = w1;
            size_t o2 = (size_t)(chv + 8) * NN + q;
            float2 x2 = *(const float2*)(xb + o2);
            float2 w2;
            w2.x = x2.x + D[fm][fn][2] * iv.x;
            w2.y = x2.y + D[fm][fn][3] * iv.y;
            *(float2*)(ob + o2) = w2;
        }
    }
}

// ---------------- launcher ----------------
extern "C" void kernel_launch(void* const* d_in, const int* in_sizes, int n_in,
                              void* d_out, int out_size) {
    const float* x  = (const float*)d_in[0];
    const float* w1 = (const float*)d_in[1];
    const float* w2 = (const float*)d_in[2];
    const float* w3 = (const float*)d_in[3];
    const float* g1 = (const float*)d_in[4];
    const float* b1 = (const float*)d_in[5];
    const float* g2 = (const float*)d_in[6];
    const float* b2 = (const float*)d_in[7];
    const float* g3 = (const float*)d_in[8];
    const float* b3 = (const float*)d_in[9];
    float* out = (float*)d_out;

    cudaFuncSetAttribute(flash_mma, cudaFuncAttributeMaxDynamicSharedMemorySize, SM_TOT);
    cudaFuncSetAttribute(qkd_mma, cudaFuncAttributeMaxDynamicSharedMemorySize, QK_SM);

    zero_kernel<<<256, 256>>>();
    convx_kernel<<<dim3(64, 4, 4), 256>>>(x);
    gram_mma<<<dim3(10, 1, 16), 256>>>(0);
    fold_kernel<<<320, 256>>>(w1, w2, w3, g1, b1, g2, b2, g3, b3);
    qkd_mma<<<dim3(5, 64), 256, QK_SM>>>(0);
    flash_mma<<<dim3(64, 4), 256, SM_TOT>>>(x, out);
}

// round 16
// speedup vs baseline: 1.2622x; 1.0636x over previous
#include <cuda_runtime.h>
#include <cuda_bf16.h>
#include <cstdint>

#define BB 4
#define CN 256
#define NN 4096
#define OTOT 320
#define BN_TOT 16384.0f
#define KTOT 16384

// ---------------- device scratch ----------------
__device__ float g_mx[CN];                            // raw channel sums
__device__ float g_G[CN * CN];
__device__ float g_Bf[OTOT];
__device__ __nv_bfloat16 g_Wh[OTOT * CN];             // folded W hi, [o][c]
__device__ __nv_bfloat16 g_Wl[OTOT * CN];             // folded W lo, [o][c]
__device__ __nv_bfloat16 g_xh[(size_t)CN * KTOT];     // x hi, [c][b*n]
__device__ __nv_bfloat16 g_xl[(size_t)CN * KTOT];     // x lo, [c][b*n]
__device__ __nv_bfloat16 g_xTh[(size_t)KTOT * CN];    // x hi, [b*n][c]
__device__ __nv_bfloat16 g_xTl[(size_t)KTOT * CN];    // x lo, [b*n][c]
__device__ __nv_bfloat16 g_Qb[(size_t)BB * NN * 64];  // [b][n][qhi32|qlo32]
__device__ __nv_bfloat16 g_Kb[(size_t)BB * NN * 64];  // [b][n][khi32|klo32]
__device__ __nv_bfloat16 g_Vb[(size_t)BB * CN * NN];  // bf16, [b][c][n]

// ---------------- mma.sync / async helpers ----------------
__device__ __forceinline__ void mma_bf16_16816(float* c, uint32_t a0, uint32_t a1,
                                               uint32_t a2, uint32_t a3,
                                               uint32_t b0, uint32_t b1) {
    asm volatile("mma.sync.aligned.m16n8k16.row.col.f32.bf16.bf16.f32 "
        "{%0,%1,%2,%3}, {%4,%5,%6,%7}, {%8,%9}, {%0,%1,%2,%3};"
        : "+f"(c[0]), "+f"(c[1]), "+f"(c[2]), "+f"(c[3])
        : "r"(a0), "r"(a1), "r"(a2), "r"(a3), "r"(b0), "r"(b1));
}
__device__ __forceinline__ void ldsm4(uint32_t& r0, uint32_t& r1, uint32_t& r2, uint32_t& r3,
                                      uint32_t a) {
    asm volatile("ldmatrix.sync.aligned.m8n8.x4.shared.b16 {%0,%1,%2,%3}, [%4];"
        : "=r"(r0), "=r"(r1), "=r"(r2), "=r"(r3) : "r"(a));
}
__device__ __forceinline__ void cp16(uint32_t dst, const void* src) {
    asm volatile("cp.async.cg.shared.global [%0], [%1], 16;" :: "r"(dst), "l"(src));
}
#define CP_COMMIT() asm volatile("cp.async.commit_group;" ::: "memory")
#define CP_WAIT0()  asm volatile("cp.async.wait_group 0;" ::: "memory")
#define CP_WAIT1()  asm volatile("cp.async.wait_group 1;" ::: "memory")
#define BAR_PAIR(id) asm volatile("bar.sync %0, 64;" :: "r"(id) : "memory")
__device__ __forceinline__ uint32_t smem_u32(const void* p) {
    uint32_t a;
    asm("{ .reg .u64 t; cvta.to.shared.u64 t, %1; cvt.u32.u64 %0, t; }" : "=r"(a) : "l"(p));
    return a;
}
__device__ __forceinline__ uint32_t pack_bf2(float a, float b) {
    __nv_bfloat162 h = __floats2bfloat162_rn(a, b);
    return *(uint32_t*)&h;
}

// ---------------- prologue ----------------
__global__ void zero_kernel() {
    int i = blockIdx.x * blockDim.x + threadIdx.x;
    g_G[i] = 0.0f;
    if (i < CN) g_mx[i] = 0.0f;
}

// tiled transpose/convert: x -> bf16 hi/lo in [c][bn] AND [bn][c]; fused channel sums
__global__ void convx_kernel(const float* __restrict__ x) {
    __shared__ float tile[64][65];
    int n0 = blockIdx.x * 64, c0 = blockIdx.y * 64, b = blockIdx.z;
    int tid = threadIdx.x;
    int rr = tid >> 6, jj = tid & 63;
    const float* xb = x + ((size_t)b * CN + c0) * NN + n0;
    #pragma unroll
    for (int r = 0; r < 16; ++r) {
        int i = r * 4 + rr;
        tile[i][jj] = xb[(size_t)i * NN + jj];
    }
    __syncthreads();
    if (tid < 64) {
        float s = 0.0f;
        #pragma unroll
        for (int j = 0; j < 64; ++j) s += tile[tid][j];
        atomicAdd(&g_mx[c0 + tid], s);
    }
    size_t bn0 = (size_t)b * NN + n0;
    #pragma unroll
    for (int r = 0; r < 16; ++r) {
        int i = r * 4 + rr;
        float v = tile[i][jj];
        __nv_bfloat16 hi = __float2bfloat16(v);
        __nv_bfloat16 lo = __float2bfloat16(v - __bfloat162float(hi));
        size_t off = (size_t)(c0 + i) * KTOT + bn0 + jj;
        g_xh[off] = hi; g_xl[off] = lo;
    }
    #pragma unroll
    for (int r = 0; r < 16; ++r) {
        int i = r * 4 + rr;           // n index
        float v = tile[jj][i];        // [c=jj][n=i]
        __nv_bfloat16 hi = __float2bfloat16(v);
        __nv_bfloat16 lo = __float2bfloat16(v - __bfloat162float(hi));
        size_t off = (bn0 + i) * CN + c0 + jj;
        g_xTh[off] = hi; g_xTl[off] = lo;
    }
}

// ---------------- Gram via mma.sync (hi/lo, symmetric, ldmatrix frags) ----------------
#define GR_STRIDE 144
#define GR_MAT (64 * GR_STRIDE)
__global__ void __launch_bounds__(256, 2)
gram_mma(int dummy) {
    __shared__ __align__(16) char smem[4 * GR_MAT];
    uint32_t sb = smem_u32(smem);
    int tid = threadIdx.x;
    int lane = tid & 31, wid = tid >> 5;
    int g = lane >> 2, t = lane & 3;
    int wm = wid >> 2, wn = wid & 3;
    int lm_r8  = (lane >> 4) << 3;
    int lm_hi  = (lane >> 3) & 1;
    int lm_row = lane & 7;
    int r4 = 0, rem = blockIdx.x;
    while (rem >= 4 - r4) { rem -= 4 - r4; ++r4; }
    int c4 = r4 + rem;
    int c0 = r4 * 64, c1 = c4 * 64;
    int kseg = blockIdx.z * 1024;

    uint32_t aoffA = (uint32_t)((wm * 32 + lm_row + lm_hi * 8) * GR_STRIDE + ((lane >> 4) << 4));
    uint32_t aoffB = (uint32_t)((wn * 16 + lm_r8 + lm_row) * GR_STRIDE + lm_hi * 16);

    float C[2][2][4] = {};

    for (int ch = 0; ch < 16; ++ch) {
        int k0 = kseg + ch * 64;
        __syncthreads();
        #pragma unroll
        for (int i = tid; i < 512; i += 256) {
            int row = i >> 3, col = i & 7;
            cp16(sb + 0 * GR_MAT + row * GR_STRIDE + col * 16,
                 g_xh + (size_t)(c0 + row) * KTOT + k0 + col * 8);
            cp16(sb + 1 * GR_MAT + row * GR_STRIDE + col * 16,
                 g_xl + (size_t)(c0 + row) * KTOT + k0 + col * 8);
            cp16(sb + 2 * GR_MAT + row * GR_STRIDE + col * 16,
                 g_xh + (size_t)(c1 + row) * KTOT + k0 + col * 8);
            cp16(sb + 3 * GR_MAT + row * GR_STRIDE + col * 16,
                 g_xl + (size_t)(c1 + row) * KTOT + k0 + col * 8);
        }
        CP_COMMIT();
        CP_WAIT0();
        __syncthreads();
        #pragma unroll
        for (int ks = 0; ks < 4; ++ks) {
            uint32_t ah[2][4], al[2][4], bh[4], bl[4];
            ldsm4(ah[0][0], ah[0][1], ah[0][2], ah[0][3], sb + 0 * GR_MAT + aoffA + ks * 32);
            ldsm4(ah[1][0], ah[1][1], ah[1][2], ah[1][3], sb + 0 * GR_MAT + aoffA + 16 * GR_STRIDE + ks * 32);
            ldsm4(al[0][0], al[0][1], al[0][2], al[0][3], sb + 1 * GR_MAT + aoffA + ks * 32);
            ldsm4(al[1][0], al[1][1], al[1][2], al[1][3], sb + 1 * GR_MAT + aoffA + 16 * GR_STRIDE + ks * 32);
            ldsm4(bh[0], bh[1], bh[2], bh[3], sb + 2 * GR_MAT + aoffB + ks * 32);
            ldsm4(bl[0], bl[1], bl[2], bl[3], sb + 3 * GR_MAT + aoffB + ks * 32);
            #pragma unroll
            for (int fn = 0; fn < 2; ++fn) {
                #pragma unroll
                for (int fm = 0; fm < 2; ++fm) {
                    mma_bf16_16816(C[fm][fn], ah[fm][0], ah[fm][1], ah[fm][2], ah[fm][3], bh[2*fn], bh[2*fn+1]);
                    mma_bf16_16816(C[fm][fn], ah[fm][0], ah[fm][1], ah[fm][2], ah[fm][3], bl[2*fn], bl[2*fn+1]);
                    mma_bf16_16816(C[fm][fn], al[fm][0], al[fm][1], al[fm][2], al[fm][3], bh[2*fn], bh[2*fn+1]);
                }
            }
        }
    }
    int mirror = (c0 != c1);
    #pragma unroll
    for (int fm = 0; fm < 2; ++fm) {
        #pragma unroll
        for (int fn = 0; fn < 2; ++fn) {
            int r0 = c0 + wm * 32 + fm * 16 + g;
            int cc = c1 + wn * 16 + fn * 8 + 2 * t;
            atomicAdd(&g_G[r0 * CN + cc],           C[fm][fn][0]);
            atomicAdd(&g_G[r0 * CN + cc + 1],       C[fm][fn][1]);
            atomicAdd(&g_G[(r0 + 8) * CN + cc],     C[fm][fn][2]);
            atomicAdd(&g_G[(r0 + 8) * CN + cc + 1], C[fm][fn][3]);
            if (mirror) {
                atomicAdd(&g_G[cc * CN + r0],           C[fm][fn][0]);
                atomicAdd(&g_G[(cc + 1) * CN + r0],     C[fm][fn][1]);
                atomicAdd(&g_G[cc * CN + r0 + 8],       C[fm][fn][2]);
                atomicAdd(&g_G[(cc + 1) * CN + r0 + 8], C[fm][fn][3]);
            }
        }
    }
}

// ---------------- fold BN (320 blocks, ILP accumulators) ----------------
__global__ void fold_kernel(const float* __restrict__ w1, const float* __restrict__ w2,
                            const float* __restrict__ w3,
                            const float* __restrict__ g1, const float* __restrict__ b1,
                            const float* __restrict__ g2, const float* __restrict__ b2,
                            const float* __restrict__ g3, const float* __restrict__ b3) {
    int o = blockIdx.x, tid = threadIdx.x;
    const float* w; float gg, bb;
    if (o < 32)      { w = w1 + o * CN;        gg = g1[o];      bb = b1[o]; }
    else if (o < 64) { w = w2 + (o - 32) * CN; gg = g2[o - 32]; bb = b2[o - 32]; }
    else             { w = w3 + (o - 64) * CN; gg = g3[o - 64]; bb = b3[o - 64]; }
    __shared__ float ws[256], redE[256], redM[256], sc_sh;
    ws[tid] = w[tid]; __syncthreads();
    float a0 = 0.0f, a1 = 0.0f, a2 = 0.0f, a3 = 0.0f;
    #pragma unroll 8
    for (int c = 0; c < CN; c += 4) {
        a0 += g_G[(c + 0) * CN + tid] * ws[c + 0];
        a1 += g_G[(c + 1) * CN + tid] * ws[c + 1];
        a2 += g_G[(c + 2) * CN + tid] * ws[c + 2];
        a3 += g_G[(c + 3) * CN + tid] * ws[c + 3];
    }
    redE[tid] = (a0 + a1 + a2 + a3) * ws[tid];
    redM[tid] = ws[tid] * g_mx[tid] * (1.0f / BN_TOT);
    __syncthreads();
    for (int st = 128; st > 0; st >>= 1) {
        if (tid < st) { redE[tid] += redE[tid + st]; redM[tid] += redM[tid + st]; }
        __syncthreads();
    }
    if (tid == 0) {
        float m = redM[0], E = redE[0] * (1.0f / BN_TOT);
        float rs = rsqrtf(E - m * m + 1e-5f);
        float sc = gg * rs;
        sc_sh = sc;
        g_Bf[o] = bb - sc * m;
    }
    __syncthreads();
    float wf = sc_sh * ws[tid];
    __nv_bfloat16 hi = __float2bfloat16(wf);
    __nv_bfloat16 lo = __float2bfloat16(wf - __bfloat162float(hi));
    g_Wh[o * CN + tid] = hi;
    g_Wl[o * CN + tid] = lo;
}

// ---------------- qkd via mma.sync + ldmatrix: Z[o][bn] = relu(W x + b) ----------------
#define QK_SM 92160
__global__ void __launch_bounds__(256, 2)
qkd_mma(int dummy) {
    extern __shared__ __align__(16) char smem[];
    uint32_t sb = smem_u32(smem);
    int tid = threadIdx.x;
    int lane = tid & 31, wid = tid >> 5;
    int g = lane >> 2, t = lane & 3;
    int wm = wid >> 2, wn = wid & 3;
    int lm_r8  = (lane >> 4) << 3;
    int lm_hi  = (lane >> 3) & 1;
    int lm_row = lane & 7;
    int o0 = blockIdx.x * 64;
    int bn0 = blockIdx.y * 256;

    uint32_t aoffW = (uint32_t)((wm * 32 + lm_row + lm_hi * 8) * 144 + ((lane >> 4) << 4));
    uint32_t aoffX = (uint32_t)((wn * 64 + lm_r8 + lm_row) * 144 + lm_hi * 16);

    float C[2][8][4] = {};

    for (int kc = 0; kc < 4; ++kc) {
        int k0 = kc * 64;
        __syncthreads();
        #pragma unroll
        for (int i = tid; i < 512; i += 256) {
            int row = i >> 3, col = i & 7;
            cp16(sb + row * 144 + col * 16,        g_Wh + (size_t)(o0 + row) * CN + k0 + col * 8);
            cp16(sb + 9216 + row * 144 + col * 16, g_Wl + (size_t)(o0 + row) * CN + k0 + col * 8);
        }
        #pragma unroll
        for (int i = tid; i < 2048; i += 256) {
            int row = i >> 3, col = i & 7;
            cp16(sb + 18432 + row * 144 + col * 16, g_xTh + (bn0 + row) * (size_t)CN + k0 + col * 8);
            cp16(sb + 55296 + row * 144 + col * 16, g_xTl + (bn0 + row) * (size_t)CN + k0 + col * 8);
        }
        CP_COMMIT();
        CP_WAIT0();
        __syncthreads();
        #pragma unroll
        for (int ks = 0; ks < 4; ++ks) {
            uint32_t ah[2][4], al[2][4];
            ldsm4(ah[0][0], ah[0][1], ah[0][2], ah[0][3], sb + aoffW + ks * 32);
            ldsm4(ah[1][0], ah[1][1], ah[1][2], ah[1][3], sb + aoffW + 16 * 144 + ks * 32);
            ldsm4(al[0][0], al[0][1], al[0][2], al[0][3], sb + 9216 + aoffW + ks * 32);
            ldsm4(al[1][0], al[1][1], al[1][2], al[1][3], sb + 9216 + aoffW + 16 * 144 + ks * 32);
            #pragma unroll
            for (int fng = 0; fng < 4; ++fng) {
                uint32_t bh[4], bl[4];
                ldsm4(bh[0], bh[1], bh[2], bh[3], sb + 18432 + aoffX + fng * (16 * 144) + ks * 32);
                ldsm4(bl[0], bl[1], bl[2], bl[3], sb + 55296 + aoffX + fng * (16 * 144) + ks * 32);
                #pragma unroll
                for (int half = 0; half < 2; ++half) {
                    int fn = fng * 2 + half;
                    #pragma unroll
                    for (int fm = 0; fm < 2; ++fm) {
                        mma_bf16_16816(C[fm][fn], ah[fm][0], ah[fm][1], ah[fm][2], ah[fm][3], bh[2*half], bh[2*half+1]);
                        mma_bf16_16816(C[fm][fn], ah[fm][0], ah[fm][1], ah[fm][2], ah[fm][3], bl[2*half], bl[2*half+1]);
                        mma_bf16_16816(C[fm][fn], al[fm][0], al[fm][1], al[fm][2], al[fm][3], bh[2*half], bh[2*half+1]);
                    }
                }
            }
        }
    }

    #pragma unroll
    for (int fm = 0; fm < 2; ++fm) {
        int obase = o0 + wm * 32 + fm * 16 + g;
        float bias0 = g_Bf[obase], bias1 = g_Bf[obase + 8];
        #pragma unroll
        for (int fn = 0; fn < 8; ++fn) {
            int bncol = bn0 + wn * 64 + fn * 8 + 2 * t;
            int b = bncol >> 12, n = bncol & 4095;
            #pragma unroll
            for (int rr = 0; rr < 2; ++rr) {
                int o = obase + rr * 8;
                float v0 = fmaxf(C[fm][fn][rr * 2 + 0] + (rr ? bias1 : bias0), 0.0f);
                float v1 = fmaxf(C[fm][fn][rr * 2 + 1] + (rr ? bias1 : bias0), 0.0f);
                if (o >= 64) {
                    *(uint32_t*)(g_Vb + ((size_t)b * CN + (o - 64)) * NN + n) = pack_bf2(v0, v1);
                } else {
                    #pragma unroll
                    for (int e = 0; e < 2; ++e) {
                        float v = e ? v1 : v0;
                        __nv_bfloat16 hi = __float2bfloat16(v);
                        __nv_bfloat16 lo = __float2bfloat16(v - __bfloat162float(hi));
                        size_t base = ((size_t)b * NN + n + e) * 64;
                        if (o < 32) {
                            g_Qb[base + o] = hi; g_Qb[base + 32 + o] = lo;
                        } else {
                            int oc = o - 32;
                            g_Kb[base + oc] = hi; g_Kb[base + 32 + oc] = lo;
                        }
                    }
                }
            }
        }
    }
}

// ---------------- flash attention: channel-major PV, NT=64, ldmatrix, compact Q/K ----------------
#define KS_OFF 0
#define KS_BUF 9216
#define VS_OFF 18432
#define VS_BUF 36864
#define PS_OFF 92160
#define STM_OFF 101376
#define STL_OFF 101888
#define STF_OFF 102400
#define FLG_OFF 102656
#define INV_OFF 102672
#define SM_TOT 102928

__global__ void __launch_bounds__(256, 2)
flash_mma(const float* __restrict__ x, float* __restrict__ out) {
    extern __shared__ __align__(16) char smem[];
    uint32_t sb = smem_u32(smem);
    int tid = threadIdx.x;
    int lane = tid & 31, wid = tid >> 5;
    int g = lane >> 2, t = lane & 3;
    int mrow = wid & 3, khalf = wid >> 2;
    int q0 = mrow * 16;
    int ch0 = wid * 32;
    int b = blockIdx.y, m0 = blockIdx.x * 64;

    float* stM = (float*)(smem + STM_OFF);
    float* stL = (float*)(smem + STL_OFF);
    float* stF = (float*)(smem + STF_OFF);
    uint32_t* flg = (uint32_t*)(smem + FLG_OFF);
    float* inv = (float*)(smem + INV_OFF);

    int lm_r8  = (lane >> 4) << 3;
    int lm_hi  = (lane >> 3) & 1;
    int lm_row = lane & 7;
    uint32_t kfrag_off = (uint32_t)((khalf * 32 + lm_r8 + lm_row) * 144 + lm_hi * 16);
    uint32_t vfrag_off = (uint32_t)((ch0 + lm_row + lm_hi * 8) * 144 + ((lane >> 4) << 4));
    uint32_t pfrag_base = sb + PS_OFF + (uint32_t)((lm_r8 + lm_row) * 144 + lm_hi * 16);

    // Q frags: [qhi32|qlo32], ksteps map {0,1,2,3,0,1}
    uint32_t qa[4][4];
    {
        const __nv_bfloat16* qr0 = g_Qb + ((size_t)b * NN + m0 + q0 + g) * 64;
        const __nv_bfloat16* qr1 = qr0 + (size_t)8 * 64;
        #pragma unroll
        for (int ks = 0; ks < 4; ++ks) {
            int e = ks * 16 + 2 * t;
            qa[ks][0] = *(const uint32_t*)(qr0 + e);
            qa[ks][1] = *(const uint32_t*)(qr1 + e);
            qa[ks][2] = *(const uint32_t*)(qr0 + e + 8);
            qa[ks][3] = *(const uint32_t*)(qr1 + e + 8);
        }
    }

    const char* kgb = (const char*)(g_Kb + ((size_t)b * NN) * 64);
    const char* vgb = (const char*)(g_Vb + (size_t)b * CN * NN);

    // prefetch chunk 0 into buf 0 (K: 64 rows x 8 cp16 = 128B; V: 256 rows x 8 cp16)
    {
        #pragma unroll
        for (int i = tid; i < 512; i += 256) {
            int row = i >> 3, col = i & 7;
            cp16(sb + KS_OFF + row * 144 + col * 16, kgb + (size_t)row * 128 + col * 16);
        }
        #pragma unroll
        for (int i = tid; i < 2048; i += 256) {
            int c = i >> 3, j = i & 7;
            cp16(sb + VS_OFF + c * 144 + j * 16, vgb + (size_t)c * (NN * 2) + j * 16);
        }
        CP_COMMIT();
    }

    float D[2][8][4];
    #pragma unroll
    for (int fm = 0; fm < 2; ++fm)
        #pragma unroll
        for (int fn = 0; fn < 8; ++fn) { D[fm][fn][0] = D[fm][fn][1] = D[fm][fn][2] = D[fm][fn][3] = 0.0f; }
    float m_run0 = -1e30f, m_run1 = -1e30f, l_run0 = 0.0f, l_run1 = 0.0f;

    const int KOFF[6] = {0, 32, 0, 32, 64, 96};
    const int QI[6]   = {0, 1, 2, 3, 0, 1};

    for (int ch = 0; ch < 64; ++ch) {
        int buf = ch & 1;
        __syncthreads();   // B1
        if (ch + 1 < 64) {
            int n1 = (ch + 1) * 64;
            uint32_t kd = sb + KS_OFF + (buf ^ 1) * KS_BUF;
            uint32_t vd = sb + VS_OFF + (buf ^ 1) * VS_BUF;
            #pragma unroll
            for (int i = tid; i < 512; i += 256) {
                int row = i >> 3, col = i & 7;
                cp16(kd + row * 144 + col * 16, kgb + (size_t)(n1 + row) * 128 + col * 16);
            }
            #pragma unroll
            for (int i = tid; i < 2048; i += 256) {
                int c = i >> 3, j = i & 7;
                cp16(vd + c * 144 + j * 16, vgb + (size_t)c * (NN * 2) + (size_t)n1 * 2 + j * 16);
            }
        }
        CP_COMMIT();
        CP_WAIT1();
        __syncthreads();   // B2

        // ---- score role: s[16q][32k] ----
        uint32_t ksmb = sb + KS_OFF + buf * KS_BUF + kfrag_off;
        float sc[4][4] = {};
        #pragma unroll
        for (int ks = 0; ks < 6; ++ks) {
            #pragma unroll
            for (int half = 0; half < 2; ++half) {
                uint32_t b00, b01, b10, b11;
                ldsm4(b00, b01, b10, b11, ksmb + half * (16 * 144) + KOFF[ks]);
                mma_bf16_16816(sc[half * 2 + 0], qa[QI[ks]][0], qa[QI[ks]][1], qa[QI[ks]][2], qa[QI[ks]][3], b00, b01);
                mma_bf16_16816(sc[half * 2 + 1], qa[QI[ks]][0], qa[QI[ks]][1], qa[QI[ks]][2], qa[QI[ks]][3], b10, b11);
            }
        }
        float mp0 = fmaxf(fmaxf(sc[0][0], sc[0][1]), fmaxf(sc[1][0], sc[1][1]));
        mp0 = fmaxf(mp0, fmaxf(fmaxf(sc[2][0], sc[2][1]), fmaxf(sc[3][0], sc[3][1])));
        float mp1 = fmaxf(fmaxf(sc[0][2], sc[0][3]), fmaxf(sc[1][2], sc[1][3]));
        mp1 = fmaxf(mp1, fmaxf(fmaxf(sc[2][2], sc[2][3]), fmaxf(sc[3][2], sc[3][3])));
        mp0 = fmaxf(mp0, __shfl_xor_sync(0xffffffffu, mp0, 1));
        mp0 = fmaxf(mp0, __shfl_xor_sync(0xffffffffu, mp0, 2));
        mp1 = fmaxf(mp1, __shfl_xor_sync(0xffffffffu, mp1, 1));
        mp1 = fmaxf(mp1, __shfl_xor_sync(0xffffffffu, mp1, 2));
        if (t == 0) {
            stM[khalf * 64 + q0 + g] = mp0;
            stM[khalf * 64 + q0 + 8 + g] = mp1;
        }
        BAR_PAIR(mrow + 1);   // pairwise stM exchange (warps mrow, mrow+4)
        float mt0 = fmaxf(stM[q0 + g], stM[64 + q0 + g]);
        float mt1 = fmaxf(stM[q0 + 8 + g], stM[64 + q0 + 8 + g]);
        float mn0 = fmaxf(m_run0, mt0), mn1 = fmaxf(m_run1, mt1);
        float f0 = __expf(m_run0 - mn0), f1 = __expf(m_run1 - mn1);
        m_run0 = mn0; m_run1 = mn1;

        float ls0 = 0.0f, ls1 = 0.0f;
        #pragma unroll
        for (int nt = 0; nt < 4; ++nt) {
            float e0 = __expf(sc[nt][0] - mn0);
            float e1 = __expf(sc[nt][1] - mn0);
            float e2 = __expf(sc[nt][2] - mn1);
            float e3 = __expf(sc[nt][3] - mn1);
            ls0 += e0 + e1; ls1 += e2 + e3;
            char* pr0 = smem + PS_OFF + (q0 + g) * 144 + khalf * 64 + nt * 16 + t * 4;
            char* pr1 = smem + PS_OFF + (q0 + 8 + g) * 144 + khalf * 64 + nt * 16 + t * 4;
            *(uint32_t*)(pr0) = pack_bf2(e0, e1);
            *(uint32_t*)(pr1) = pack_bf2(e2, e3);
        }
        uint32_t nb = __ballot_sync(0xffffffffu, (f0 < 1.0f) || (f1 < 1.0f));
        if (khalf == 0 && t == 0) {
            stF[q0 + g] = f0;
            stF[q0 + 8 + g] = f1;
        }
        if (khalf == 0 && lane == 0) flg[mrow] = nb;
        ls0 += __shfl_xor_sync(0xffffffffu, ls0, 1);
        ls0 += __shfl_xor_sync(0xffffffffu, ls0, 2);
        ls1 += __shfl_xor_sync(0xffffffffu, ls1, 1);
        ls1 += __shfl_xor_sync(0xffffffffu, ls1, 2);
        if (t == 0) {
            stL[khalf * 64 + q0 + g] = ls0;
            stL[khalf * 64 + q0 + 8 + g] = ls1;
        }
        __syncthreads();   // B4: Ps both halves + stL + stF + flags visible
        l_run0 = l_run0 * f0 + stL[q0 + g] + stL[64 + q0 + g];
        l_run1 = l_run1 * f1 + stL[q0 + 8 + g] + stL[64 + q0 + 8 + g];

        // ---- PV role: D[32ch][64q] += V[32ch][64k] * P[64k][64q] ----
        if (flg[0] | flg[1] | flg[2] | flg[3]) {
            #pragma unroll
            for (int fn = 0; fn < 8; ++fn) {
                float2 ff = *(float2*)(stF + fn * 8 + 2 * t);
                #pragma unroll
                for (int fm = 0; fm < 2; ++fm) {
                    D[fm][fn][0] *= ff.x; D[fm][fn][1] *= ff.y;
                    D[fm][fn][2] *= ff.x; D[fm][fn][3] *= ff.y;
                }
            }
        }
        uint32_t vsmb = sb + VS_OFF + buf * VS_BUF + vfrag_off;
        #pragma unroll
        for (int ks = 0; ks < 4; ++ks) {
            uint32_t va[2][4];
            ldsm4(va[0][0], va[0][1], va[0][2], va[0][3], vsmb + ks * 32);
            ldsm4(va[1][0], va[1][1], va[1][2], va[1][3], vsmb + 16 * 144 + ks * 32);
            #pragma unroll
            for (int fnp = 0; fnp < 4; ++fnp) {
                uint32_t p00, p01, p10, p11;
                ldsm4(p00, p01, p10, p11, pfrag_base + fnp * (16 * 144) + ks * 32);
                mma_bf16_16816(D[0][fnp * 2 + 0], va[0][0], va[0][1], va[0][2], va[0][3], p00, p01);
                mma_bf16_16816(D[1][fnp * 2 + 0], va[1][0], va[1][1], va[1][2], va[1][3], p00, p01);
                mma_bf16_16816(D[0][fnp * 2 + 1], va[0][0], va[0][1], va[0][2], va[0][3], p10, p11);
                mma_bf16_16816(D[1][fnp * 2 + 1], va[1][0], va[1][1], va[1][2], va[1][3], p10, p11);
            }
        }
    }

    if (khalf == 0 && t == 0) {
        inv[q0 + g] = 1.0f / l_run0;
        inv[q0 + 8 + g] = 1.0f / l_run1;
    }
    __syncthreads();

    const float* xb = x + (size_t)b * CN * NN + m0;
    float* ob = out + (size_t)b * CN * NN + m0;
    #pragma unroll
    for (int fn = 0; fn < 8; ++fn) {
        int q = fn * 8 + 2 * t;
        float2 iv = *(float2*)(inv + q);
        #pragma unroll
        for (int fm = 0; fm < 2; ++fm) {
            int chv = ch0 + fm * 16 + g;
            size_t o1 = (size_t)chv * NN + q;
            float2 x1 = *(const float2*)(xb + o1);
            float2 w1;
            w1.x = x1.x + D[fm][fn][0] * iv.x;
            w1.y = x1.y + D[fm][fn][1] * iv.y;
            *(float2*)(ob + o1) = w1;
            size_t o2 = (size_t)(chv + 8) * NN + q;
            float2 x2 = *(const float2*)(xb + o2);
            float2 w2;
            w2.x = x2.x + D[fm][fn][2] * iv.x;
            w2.y = x2.y + D[fm][fn][3] * iv.y;
            *(float2*)(ob + o2) = w2;
        }
    }
}

// ---------------- launcher ----------------
extern "C" void kernel_launch(void* const* d_in, const int* in_sizes, int n_in,
                              void* d_out, int out_size) {
    const float* x  = (const float*)d_in[0];
    const float* w1 = (const float*)d_in[1];
    const float* w2 = (const float*)d_in[2];
    const float* w3 = (const float*)d_in[3];
    const float* g1 = (const float*)d_in[4];
    const float* b1 = (const float*)d_in[5];
    const float* g2 = (const float*)d_in[6];
    const float* b2 = (const float*)d_in[7];
    const float* g3 = (const float*)d_in[8];
    const float* b3 = (const float*)d_in[9];
    float* out = (float*)d_out;

    cudaFuncSetAttribute(flash_mma, cudaFuncAttributeMaxDynamicSharedMemorySize, SM_TOT);
    cudaFuncSetAttribute(qkd_mma, cudaFuncAttributeMaxDynamicSharedMemorySize, QK_SM);

    zero_kernel<<<256, 256>>>();
    convx_kernel<<<dim3(64, 4, 4), 256>>>(x);
    gram_mma<<<dim3(10, 1, 16), 256>>>(0);
    fold_kernel<<<320, 256>>>(w1, w2, w3, g1, b1, g2, b2, g3, b3);
    qkd_mma<<<dim3(5, 64), 256, QK_SM>>>(0);
    flash_mma<<<dim3(64, 4), 256, SM_TOT>>>(x, out);
}